// round 6
// baseline (speedup 1.0000x reference)
#include <cuda_runtime.h>
#include <math.h>

// ---------------- Problem constants ----------------
#define BB 32
#define SS 11
#define NN 4096
#define DD 512
#define MLPD 2048
#define MROWS (BB*NN)          // 131072
#define SROWS (BB*SS)          // 352
#define NCHUNK 16              // n-chunks per batch (4096/256)
#define EPS_LN 1e-5f
#define EPS_ATTN 1e-8f

// ---------------- Scratch (device globals; no allocation allowed) ----------------
__device__ float g_xln[MROWS*DD];          // 256 MB  normalized inputs
__device__ float g_kv[MROWS*2*DD];         // 512 MB  [k | v] per input row
__device__ float g_q[SROWS*DD];
__device__ float g_attn[BB*NN*16];         // softmax probs, s-padded to 16 (pad stays 0)
__device__ float g_lpart[BB*NCHUNK*16];    // per-chunk per-s sums for renorm
__device__ float g_inv[SROWS];             // 1/(sum+eps)
__device__ float g_upart[BB*NCHUNK*SS*DD]; // partial updates
__device__ float g_upd[SROWS*DD];
__device__ float g_gi[SROWS*3*DD];
__device__ float g_gh[SROWS*3*DD];
__device__ float g_stmp[SROWS*DD];
__device__ float g_sA[SROWS*DD];
__device__ float g_sB[SROWS*DD];
__device__ float g_lnb[SROWS*DD];
__device__ float g_h1[SROWS*MLPD];

// ---------------- Row LayerNorm (rows of 512) ----------------
__global__ void __launch_bounds__(256) rowln_kernel(
    const float* __restrict__ X, const float* __restrict__ g,
    const float* __restrict__ b, float* __restrict__ out)
{
    int row = blockIdx.x;
    int t = threadIdx.x;
    const float* x = X + (size_t)row * DD;
    float v0 = x[t], v1 = x[t + 256];
    float s = v0 + v1;
    float sq = v0 * v0 + v1 * v1;
    int w = t >> 5, lane = t & 31;
    #pragma unroll
    for (int o = 16; o; o >>= 1) {
        s  += __shfl_xor_sync(0xffffffffu, s, o);
        sq += __shfl_xor_sync(0xffffffffu, sq, o);
    }
    __shared__ float shs[8], shq[8];
    __shared__ float mu_s, rs_s;
    if (lane == 0) { shs[w] = s; shq[w] = sq; }
    __syncthreads();
    if (t == 0) {
        float S = 0.f, Q = 0.f;
        #pragma unroll
        for (int i = 0; i < 8; i++) { S += shs[i]; Q += shq[i]; }
        float mu = S * (1.f / DD);
        float var = Q * (1.f / DD) - mu * mu;
        mu_s = mu;
        rs_s = rsqrtf(var + EPS_LN);
    }
    __syncthreads();
    float mu = mu_s, rs = rs_s;
    float* o = out + (size_t)row * DD;
    o[t]       = (v0 - mu) * rs * g[t]       + b[t];
    o[t + 256] = (v1 - mu) * rs * g[t + 256] + b[t + 256];
}

// ---------------- Big fp32 GEMM: g_kv = g_xln @ [Wk | Wv] + [bk | bv] ----------------
// 128x128x16 tiles, 256 threads, 8x8 per thread.
__global__ void __launch_bounds__(256) kv_gemm_kernel(
    const float* __restrict__ A,
    const float* __restrict__ Wk, const float* __restrict__ Wv,
    const float* __restrict__ bk, const float* __restrict__ bv,
    float* __restrict__ C)
{
    __shared__ __align__(16) float As[16][132];
    __shared__ __align__(16) float Bs[16][132];
    int m0 = blockIdx.x * 128;
    int by = blockIdx.y;                 // 0..7; 0-3 -> Wk, 4-7 -> Wv
    const float* W; const float* bias; int c0;
    if (by < 4) { W = Wk; bias = bk; c0 = by * 128; }
    else        { W = Wv; bias = bv; c0 = (by - 4) * 128; }
    int t = threadIdx.x;
    int tx = t & 15, ty = t >> 4;

    float acc[8][8];
    #pragma unroll
    for (int i = 0; i < 8; i++)
        #pragma unroll
        for (int j = 0; j < 8; j++) acc[i][j] = 0.f;

    for (int k0 = 0; k0 < DD; k0 += 16) {
        // A tile: 128x16 -> 512 float4, 2 per thread
        #pragma unroll
        for (int i = 0; i < 2; i++) {
            int idx4 = t + i * 256;
            int m = idx4 >> 2, k4 = idx4 & 3;
            float4 v = *(const float4*)(A + (size_t)(m0 + m) * DD + k0 + k4 * 4);
            As[k4 * 4 + 0][m] = v.x;
            As[k4 * 4 + 1][m] = v.y;
            As[k4 * 4 + 2][m] = v.z;
            As[k4 * 4 + 3][m] = v.w;
        }
        // B tile: 16x128
        #pragma unroll
        for (int i = 0; i < 2; i++) {
            int idx4 = t + i * 256;
            int k = idx4 >> 5, n4 = idx4 & 31;
            float4 v = *(const float4*)(W + (size_t)(k0 + k) * DD + c0 + n4 * 4);
            *(float4*)&Bs[k][n4 * 4] = v;
        }
        __syncthreads();
        #pragma unroll
        for (int kk = 0; kk < 16; kk++) {
            float a[8], bf[8];
            *(float4*)&a[0]  = *(const float4*)&As[kk][ty * 4];
            *(float4*)&a[4]  = *(const float4*)&As[kk][64 + ty * 4];
            *(float4*)&bf[0] = *(const float4*)&Bs[kk][tx * 4];
            *(float4*)&bf[4] = *(const float4*)&Bs[kk][64 + tx * 4];
            #pragma unroll
            for (int i = 0; i < 8; i++)
                #pragma unroll
                for (int j = 0; j < 8; j++)
                    acc[i][j] = fmaf(a[i], bf[j], acc[i][j]);
        }
        __syncthreads();
    }
    // epilogue
    #pragma unroll
    for (int ih = 0; ih < 2; ih++) {
        #pragma unroll
        for (int ii = 0; ii < 4; ii++) {
            int m = m0 + ih * 64 + ty * 4 + ii;
            #pragma unroll
            for (int jh = 0; jh < 2; jh++) {
                int cl = jh * 64 + tx * 4;   // local col in 128 tile
                float4 o;
                o.x = acc[ih * 4 + ii][jh * 4 + 0] + bias[c0 + cl + 0];
                o.y = acc[ih * 4 + ii][jh * 4 + 1] + bias[c0 + cl + 1];
                o.z = acc[ih * 4 + ii][jh * 4 + 2] + bias[c0 + cl + 2];
                o.w = acc[ih * 4 + ii][jh * 4 + 3] + bias[c0 + cl + 3];
                *(float4*)(C + (size_t)m * (2 * DD) + by * 128 + cl) = o;
            }
        }
    }
}

// ---------------- Generic small GEMM: C[M,N] = scale*(A@op(B)) + bias, opt relu ----
// 64x64x16 tiles, 256 threads, 4x4 per thread. K must be multiple of 16.
__global__ void __launch_bounds__(256) gemm_small_kernel(
    const float* __restrict__ A, const float* __restrict__ Bm,
    const float* __restrict__ bias, float* __restrict__ C,
    int M, int N, int K, int transB, float scale, int relu)
{
    __shared__ float As[16][68];
    __shared__ float Bs[16][68];
    int m0 = blockIdx.x * 64, n0 = blockIdx.y * 64;
    int t = threadIdx.x;
    int tx = t & 15, ty = t >> 4;
    float acc[4][4];
    #pragma unroll
    for (int i = 0; i < 4; i++)
        #pragma unroll
        for (int j = 0; j < 4; j++) acc[i][j] = 0.f;

    for (int k0 = 0; k0 < K; k0 += 16) {
        #pragma unroll
        for (int i = 0; i < 4; i++) {
            int idx = t + i * 256;
            int m = idx >> 4, k = idx & 15;
            As[k][m] = (m0 + m < M) ? A[(size_t)(m0 + m) * K + k0 + k] : 0.f;
        }
        if (!transB) {
            #pragma unroll
            for (int i = 0; i < 4; i++) {
                int idx = t + i * 256;
                int k = idx >> 6, n = idx & 63;
                Bs[k][n] = (n0 + n < N) ? Bm[(size_t)(k0 + k) * N + n0 + n] : 0.f;
            }
        } else {
            #pragma unroll
            for (int i = 0; i < 4; i++) {
                int idx = t + i * 256;
                int n = idx >> 4, k = idx & 15;
                Bs[k][n] = (n0 + n < N) ? Bm[(size_t)(n0 + n) * K + k0 + k] : 0.f;
            }
        }
        __syncthreads();
        #pragma unroll
        for (int kk = 0; kk < 16; kk++) {
            float a[4], bf[4];
            #pragma unroll
            for (int i = 0; i < 4; i++) a[i]  = As[kk][ty * 4 + i];
            #pragma unroll
            for (int j = 0; j < 4; j++) bf[j] = Bs[kk][tx * 4 + j];
            #pragma unroll
            for (int i = 0; i < 4; i++)
                #pragma unroll
                for (int j = 0; j < 4; j++)
                    acc[i][j] = fmaf(a[i], bf[j], acc[i][j]);
        }
        __syncthreads();
    }
    #pragma unroll
    for (int i = 0; i < 4; i++) {
        int m = m0 + ty * 4 + i;
        if (m >= M) continue;
        #pragma unroll
        for (int j = 0; j < 4; j++) {
            int n = n0 + tx * 4 + j;
            if (n >= N) continue;
            float v = acc[i][j] * scale + (bias ? bias[n] : 0.f);
            if (relu) v = fmaxf(v, 0.f);
            C[(size_t)m * N + n] = v;
        }
    }
}

// ---------------- Fused logits + softmax(over S) + renorm partials ----------------
// Block = (batch b, n-chunk of 256). Tile 16(s, padded) x 256(n), K-chunks of 16.
__global__ void __launch_bounds__(256) logits_softmax_kernel(
    const float* __restrict__ q, const float* __restrict__ kv,
    float* __restrict__ attn, float* __restrict__ lpart)
{
    int b = blockIdx.x, chunk = blockIdx.y;
    __shared__ __align__(16) float Qs[16 * 20];
    __shared__ __align__(16) float Ks[16 * 260];
    int t = threadIdx.x;
    int tx = t & 63, sg = t >> 6;
    int n0 = chunk * 256;
    const float* kb = kv + ((size_t)b * NN + n0) * (2 * DD);

    float acc[4][4];
    #pragma unroll
    for (int i = 0; i < 4; i++)
        #pragma unroll
        for (int j = 0; j < 4; j++) acc[i][j] = 0.f;

    for (int k0 = 0; k0 < DD; k0 += 16) {
        { // Q chunk 16k x 16s (pad rows s>=11 with 0)
            int k = t & 15, s = t >> 4;
            Qs[k * 20 + s] = (s < SS) ? q[((size_t)(b * SS + s)) * DD + k0 + k] : 0.f;
        }
        #pragma unroll
        for (int i = 0; i < 4; i++) { // K chunk: 256n x 16k
            int idx4 = t + i * 256;
            int n = idx4 >> 2, k4 = idx4 & 3;
            float4 v = *(const float4*)(kb + (size_t)n * (2 * DD) + k0 + k4 * 4);
            Ks[(k4 * 4 + 0) * 260 + n] = v.x;
            Ks[(k4 * 4 + 1) * 260 + n] = v.y;
            Ks[(k4 * 4 + 2) * 260 + n] = v.z;
            Ks[(k4 * 4 + 3) * 260 + n] = v.w;
        }
        __syncthreads();
        #pragma unroll
        for (int kk = 0; kk < 16; kk++) {
            float qv[4], kvv[4];
            *(float4*)qv  = *(const float4*)&Qs[kk * 20 + sg * 4];
            *(float4*)kvv = *(const float4*)&Ks[kk * 260 + tx * 4];
            #pragma unroll
            for (int i = 0; i < 4; i++)
                #pragma unroll
                for (int j = 0; j < 4; j++)
                    acc[i][j] = fmaf(qv[i], kvv[j], acc[i][j]);
        }
        __syncthreads();
    }

    // stash logits tile into shared (reuse Ks as [s][n])
    #pragma unroll
    for (int i = 0; i < 4; i++)
        #pragma unroll
        for (int j = 0; j < 4; j++)
            Ks[(sg * 4 + i) * 260 + tx * 4 + j] = acc[i][j];
    __syncthreads();

    // per-n softmax over s (each of the 256 threads owns one n)
    float p[SS];
    {
        int n = t;
        float m = -1e30f;
        #pragma unroll
        for (int s = 0; s < SS; s++) m = fmaxf(m, Ks[s * 260 + n]);
        float sum = 0.f;
        #pragma unroll
        for (int s = 0; s < SS; s++) { float e = __expf(Ks[s * 260 + n] - m); p[s] = e; sum += e; }
        float r = 1.f / sum;
        float* ar = attn + ((size_t)b * NN + n0 + n) * 16;
        #pragma unroll
        for (int s = 0; s < SS; s++) { p[s] *= r; ar[s] = p[s]; }
    }
    __syncthreads();
    #pragma unroll
    for (int s = 0; s < SS; s++) Ks[s * 260 + t] = p[s];
    __syncthreads();

    // deterministic per-block column sums (renorm partials)
    int w = t >> 5, lane = t & 31;
    for (int s = w; s < SS; s += 8) {
        float v = 0.f;
        #pragma unroll
        for (int i = 0; i < 8; i++) v += Ks[s * 260 + lane + i * 32];
        #pragma unroll
        for (int o = 16; o; o >>= 1) v += __shfl_xor_sync(0xffffffffu, v, o);
        if (lane == 0) lpart[(b * NCHUNK + chunk) * 16 + s] = v;
    }
}

// ---------------- inv = 1/(sum_n attn + eps) ----------------
__global__ void inv_kernel(const float* __restrict__ lpart, float* __restrict__ inv)
{
    int t = threadIdx.x;
    if (t < SROWS) {
        int b = t / SS, s = t % SS;
        float sum = 0.f;
        #pragma unroll
        for (int c = 0; c < NCHUNK; c++) sum += lpart[(b * NCHUNK + c) * 16 + s];
        inv[t] = 1.f / (sum + EPS_ATTN);
    }
}

// ---------------- updates partials: upart[b,chunk,s,:] = sum_{n in chunk} p[s,n]*v[n,:] ----
__device__ __forceinline__ void fma4(float4& a, float s, float4 v) {
    a.x = fmaf(s, v.x, a.x); a.y = fmaf(s, v.y, a.y);
    a.z = fmaf(s, v.z, a.z); a.w = fmaf(s, v.w, a.w);
}

__global__ void __launch_bounds__(128) updates_kernel(
    const float* __restrict__ kv, const float* __restrict__ attn,
    float* __restrict__ upart)
{
    int b = blockIdx.x, chunk = blockIdx.y, t = threadIdx.x;
    float4 acc[SS];
    #pragma unroll
    for (int s = 0; s < SS; s++) acc[s] = make_float4(0.f, 0.f, 0.f, 0.f);
    const float* vb = kv + (size_t)b * NN * (2 * DD) + DD;  // v half
    const float* pb = attn + (size_t)b * NN * 16;
    int n0 = chunk * 256;
    for (int n = n0; n < n0 + 256; n++) {
        float4 v = *(const float4*)(vb + (size_t)n * (2 * DD) + t * 4);
        const float* pr = pb + (size_t)n * 16;
        float4 p0 = *(const float4*)(pr);
        float4 p1 = *(const float4*)(pr + 4);
        float4 p2 = *(const float4*)(pr + 8);
        fma4(acc[0],  p0.x, v); fma4(acc[1],  p0.y, v);
        fma4(acc[2],  p0.z, v); fma4(acc[3],  p0.w, v);
        fma4(acc[4],  p1.x, v); fma4(acc[5],  p1.y, v);
        fma4(acc[6],  p1.z, v); fma4(acc[7],  p1.w, v);
        fma4(acc[8],  p2.x, v); fma4(acc[9],  p2.y, v);
        fma4(acc[10], p2.z, v);
    }
    #pragma unroll
    for (int s = 0; s < SS; s++)
        *(float4*)(upart + ((size_t)((b * NCHUNK + chunk) * SS + s)) * DD + t * 4) = acc[s];
}

// ---------------- reduce partials + apply renorm ----------------
__global__ void __launch_bounds__(128) upd_reduce_kernel(
    const float* __restrict__ upart, const float* __restrict__ inv,
    float* __restrict__ upd)
{
    int row = blockIdx.x;               // 0..351
    int b = row / SS, s = row % SS;
    int t = threadIdx.x;
    float4 acc = make_float4(0.f, 0.f, 0.f, 0.f);
    for (int c = 0; c < NCHUNK; c++) {
        float4 v = *(const float4*)(upart + ((size_t)((b * NCHUNK + c) * SS + s)) * DD + t * 4);
        acc.x += v.x; acc.y += v.y; acc.z += v.z; acc.w += v.w;
    }
    float iv = inv[row];
    acc.x *= iv; acc.y *= iv; acc.z *= iv; acc.w *= iv;
    *(float4*)(upd + (size_t)row * DD + t * 4) = acc;
}

// ---------------- GRU elementwise ----------------
__global__ void __launch_bounds__(256) gru_kernel(
    const float* __restrict__ gi, const float* __restrict__ gh,
    const float* __restrict__ slots, float* __restrict__ out)
{
    int idx = blockIdx.x * 256 + threadIdx.x;
    if (idx >= SROWS * DD) return;
    int row = idx >> 9, d = idx & 511;
    size_t base = (size_t)row * (3 * DD);
    float ir = gi[base + d], iz = gi[base + DD + d], inn = gi[base + 2 * DD + d];
    float hr = gh[base + d], hz = gh[base + DD + d], hn = gh[base + 2 * DD + d];
    float r = 1.f / (1.f + __expf(-(ir + hr)));
    float z = 1.f / (1.f + __expf(-(iz + hz)));
    float nn = tanhf(inn + r * hn);
    out[idx] = (1.f - z) * nn + z * slots[idx];
}

// ---------------- Host orchestration ----------------
extern "C" void kernel_launch(void* const* d_in, const int* in_sizes, int n_in,
                              void* d_out, int out_size)
{
    const float* slots0  = (const float*)d_in[0];
    const float* inputs  = (const float*)d_in[1];
    const float* ln_in_g = (const float*)d_in[2];
    const float* ln_in_b = (const float*)d_in[3];
    const float* Wk      = (const float*)d_in[4];
    const float* bk      = (const float*)d_in[5];
    const float* Wv      = (const float*)d_in[6];
    const float* bv      = (const float*)d_in[7];
    const float* ln_q_g  = (const float*)d_in[8];
    const float* ln_q_b  = (const float*)d_in[9];
    const float* Wq      = (const float*)d_in[10];
    const float* W_ih    = (const float*)d_in[11];
    const float* b_ih    = (const float*)d_in[12];
    const float* W_hh    = (const float*)d_in[13];
    const float* b_hh    = (const float*)d_in[14];
    const float* ln_m_g  = (const float*)d_in[15];
    const float* ln_m_b  = (const float*)d_in[16];
    const float* W1      = (const float*)d_in[17];
    const float* b1      = (const float*)d_in[18];
    const float* W2      = (const float*)d_in[19];
    const float* b2      = (const float*)d_in[20];
    float* out = (float*)d_out;

    float *xln, *kvp, *qp, *attn, *lpart, *invp, *upart, *upd, *gi, *gh;
    float *stmp, *sA, *sB, *lnb, *h1;
    cudaGetSymbolAddress((void**)&xln,  g_xln);
    cudaGetSymbolAddress((void**)&kvp,  g_kv);
    cudaGetSymbolAddress((void**)&qp,   g_q);
    cudaGetSymbolAddress((void**)&attn, g_attn);
    cudaGetSymbolAddress((void**)&lpart,g_lpart);
    cudaGetSymbolAddress((void**)&invp, g_inv);
    cudaGetSymbolAddress((void**)&upart,g_upart);
    cudaGetSymbolAddress((void**)&upd,  g_upd);
    cudaGetSymbolAddress((void**)&gi,   g_gi);
    cudaGetSymbolAddress((void**)&gh,   g_gh);
    cudaGetSymbolAddress((void**)&stmp, g_stmp);
    cudaGetSymbolAddress((void**)&sA,   g_sA);
    cudaGetSymbolAddress((void**)&sB,   g_sB);
    cudaGetSymbolAddress((void**)&lnb,  g_lnb);
    cudaGetSymbolAddress((void**)&h1,   g_h1);

    const float qscale = 0.044194173824159216f; // 1/sqrt(512)

    // one-time: input LN + k/v projections
    rowln_kernel<<<MROWS, 256>>>(inputs, ln_in_g, ln_in_b, xln);
    kv_gemm_kernel<<<dim3(MROWS / 128, 8), 256>>>(xln, Wk, Wv, bk, bv, kvp);

    const float* cur = slots0;
    for (int it = 0; it < 3; it++) {
        // q = LN(slots) @ Wq * scale
        rowln_kernel<<<SROWS, 256>>>(cur, ln_q_g, ln_q_b, lnb);
        gemm_small_kernel<<<dim3(6, 8), 256>>>(lnb, Wq, nullptr, qp,
                                               SROWS, DD, DD, 0, qscale, 0);
        // inverted attention
        logits_softmax_kernel<<<dim3(BB, NCHUNK), 256>>>(qp, kvp, attn, lpart);
        inv_kernel<<<1, 384>>>(lpart, invp);
        updates_kernel<<<dim3(BB, NCHUNK), 128>>>(kvp, attn, upart);
        upd_reduce_kernel<<<SROWS, 128>>>(upart, invp, upd);
        // GRU
        gemm_small_kernel<<<dim3(6, 24), 256>>>(upd, W_ih, b_ih, gi,
                                                SROWS, 3 * DD, DD, 1, 1.f, 0);
        gemm_small_kernel<<<dim3(6, 24), 256>>>(cur, W_hh, b_hh, gh,
                                                SROWS, 3 * DD, DD, 1, 1.f, 0);
        gru_kernel<<<(SROWS * DD + 255) / 256, 256>>>(gi, gh, cur, stmp);
        // MLP (no residual)
        rowln_kernel<<<SROWS, 256>>>(stmp, ln_m_g, ln_m_b, lnb);
        gemm_small_kernel<<<dim3(6, 32), 256>>>(lnb, W1, b1, h1,
                                                SROWS, MLPD, DD, 0, 1.f, 1);
        float* nxt = (it == 2) ? out : (it == 0 ? sA : sB);
        gemm_small_kernel<<<dim3(6, 8), 256>>>(h1, W2, b2, nxt,
                                               SROWS, DD, MLPD, 0, 1.f, 0);
        cur = nxt;
    }
}

// round 7
// speedup vs baseline: 2.3064x; 2.3064x over previous
#include <cuda_runtime.h>
#include <math.h>
#include <stdint.h>

// ---------------- Problem constants ----------------
#define BB 32
#define SS 11
#define NN 4096
#define DD 512
#define MLPD 2048
#define MROWS (BB*NN)          // 131072
#define SROWS (BB*SS)          // 352
#define NCHUNK 16              // n-chunks per batch (4096/256)
#define EPS_LN 1e-5f
#define EPS_ATTN 1e-8f

// ---------------- Scratch (device globals; no allocation allowed) ----------------
__device__ float g_xln[MROWS*DD];          // 256 MB  normalized inputs
__device__ float g_kv[MROWS*2*DD];         // 512 MB  [k | v] per input row
__device__ float g_q[SROWS*DD];
__device__ float g_attn[BB*NN*16];         // softmax probs, s-padded to 16 (pad stays 0)
__device__ float g_lpart[BB*NCHUNK*16];    // per-chunk per-s sums for renorm
__device__ float g_inv[SROWS];             // 1/(sum+eps)
__device__ float g_upart[BB*NCHUNK*SS*DD]; // partial updates
__device__ float g_upd[SROWS*DD];
__device__ float g_gi[SROWS*3*DD];
__device__ float g_gh[SROWS*3*DD];
__device__ float g_stmp[SROWS*DD];
__device__ float g_sA[SROWS*DD];
__device__ float g_sB[SROWS*DD];
__device__ float g_lnb[SROWS*DD];
__device__ float g_h1[SROWS*MLPD];

// ---------------- helpers ----------------
__device__ __forceinline__ uint32_t f2tf32(float x) {
    uint32_t r;
    asm("cvt.rna.tf32.f32 %0, %1;" : "=r"(r) : "f"(x));
    return r;
}

// ---------------- Row LayerNorm (rows of 512) ----------------
__global__ void __launch_bounds__(256) rowln_kernel(
    const float* __restrict__ X, const float* __restrict__ g,
    const float* __restrict__ b, float* __restrict__ out)
{
    int row = blockIdx.x;
    int t = threadIdx.x;
    const float* x = X + (size_t)row * DD;
    float v0 = x[t], v1 = x[t + 256];
    float s = v0 + v1;
    float sq = v0 * v0 + v1 * v1;
    int w = t >> 5, lane = t & 31;
    #pragma unroll
    for (int o = 16; o; o >>= 1) {
        s  += __shfl_xor_sync(0xffffffffu, s, o);
        sq += __shfl_xor_sync(0xffffffffu, sq, o);
    }
    __shared__ float shs[8], shq[8];
    __shared__ float mu_s, rs_s;
    if (lane == 0) { shs[w] = s; shq[w] = sq; }
    __syncthreads();
    if (t == 0) {
        float S = 0.f, Q = 0.f;
        #pragma unroll
        for (int i = 0; i < 8; i++) { S += shs[i]; Q += shq[i]; }
        float mu = S * (1.f / DD);
        float var = Q * (1.f / DD) - mu * mu;
        mu_s = mu;
        rs_s = rsqrtf(var + EPS_LN);
    }
    __syncthreads();
    float mu = mu_s, rs = rs_s;
    float* o = out + (size_t)row * DD;
    o[t]       = (v0 - mu) * rs * g[t]       + b[t];
    o[t + 256] = (v1 - mu) * rs * g[t + 256] + b[t + 256];
}

// ---------------- tf32 tensor-core GEMM: g_kv = g_xln @ [Wk|Wv] + [bk|bv] --------
// 128x128 block tile, BK=16, 256 threads (8 warps as 2m x 4n, warp tile 64x32).
// mma.sync.m16n8k8 tf32, fp32 accumulate.
__global__ void __launch_bounds__(256) kv_gemm_tf32_kernel(
    const float* __restrict__ A,
    const float* __restrict__ Wk, const float* __restrict__ Wv,
    const float* __restrict__ bk, const float* __restrict__ bv,
    float* __restrict__ C)
{
    __shared__ uint32_t As[16][136];   // [k][m], stride 136 -> conflict-free frag loads
    __shared__ uint32_t Bs[16][136];   // [k][n]
    int m0 = blockIdx.x * 128;
    int by = blockIdx.y;               // 0..7; 0-3 -> Wk, 4-7 -> Wv
    const float* W; const float* bias; int cb;
    if (by < 4) { W = Wk; bias = bk; cb = by * 128; }
    else        { W = Wv; bias = bv; cb = (by - 4) * 128; }
    int outc0 = by * 128;              // column base in C's 1024-wide row

    int t = threadIdx.x;
    int warp = t >> 5, lane = t & 31;
    int wm = (warp & 1) * 64;          // warp m offset
    int wn = (warp >> 1) * 32;         // warp n offset
    int g = lane >> 2, t4 = lane & 3;

    float c[4][4][4];
    #pragma unroll
    for (int i = 0; i < 4; i++)
        #pragma unroll
        for (int j = 0; j < 4; j++)
            #pragma unroll
            for (int r = 0; r < 4; r++) c[i][j][r] = 0.f;

    for (int k0 = 0; k0 < DD; k0 += 16) {
        // prefetch global -> regs
        float4 av[2], bv4[2];
        int am[2], ak4[2], bk_[2], bn4[2];
        #pragma unroll
        for (int i = 0; i < 2; i++) {
            int idx4 = t + i * 256;
            am[i] = idx4 >> 2; ak4[i] = idx4 & 3;
            av[i] = *(const float4*)(A + (size_t)(m0 + am[i]) * DD + k0 + ak4[i] * 4);
        }
        #pragma unroll
        for (int i = 0; i < 2; i++) {
            int idx4 = t + i * 256;
            bk_[i] = idx4 >> 5; bn4[i] = idx4 & 31;
            bv4[i] = *(const float4*)(W + (size_t)(k0 + bk_[i]) * DD + cb + bn4[i] * 4);
        }
        __syncthreads();   // prior iteration's compute done
        #pragma unroll
        for (int i = 0; i < 2; i++) {
            As[ak4[i] * 4 + 0][am[i]] = f2tf32(av[i].x);
            As[ak4[i] * 4 + 1][am[i]] = f2tf32(av[i].y);
            As[ak4[i] * 4 + 2][am[i]] = f2tf32(av[i].z);
            As[ak4[i] * 4 + 3][am[i]] = f2tf32(av[i].w);
            Bs[bk_[i]][bn4[i] * 4 + 0] = f2tf32(bv4[i].x);
            Bs[bk_[i]][bn4[i] * 4 + 1] = f2tf32(bv4[i].y);
            Bs[bk_[i]][bn4[i] * 4 + 2] = f2tf32(bv4[i].z);
            Bs[bk_[i]][bn4[i] * 4 + 3] = f2tf32(bv4[i].w);
        }
        __syncthreads();

        #pragma unroll
        for (int ks = 0; ks < 2; ks++) {
            int kb = ks * 8;
            uint32_t a[4][4], bf[4][2];
            #pragma unroll
            for (int i = 0; i < 4; i++) {
                int mb = wm + i * 16;
                a[i][0] = As[kb + t4][mb + g];
                a[i][1] = As[kb + t4][mb + g + 8];
                a[i][2] = As[kb + t4 + 4][mb + g];
                a[i][3] = As[kb + t4 + 4][mb + g + 8];
            }
            #pragma unroll
            for (int j = 0; j < 4; j++) {
                int nb = wn + j * 8;
                bf[j][0] = Bs[kb + t4][nb + g];
                bf[j][1] = Bs[kb + t4 + 4][nb + g];
            }
            #pragma unroll
            for (int i = 0; i < 4; i++)
                #pragma unroll
                for (int j = 0; j < 4; j++) {
                    asm volatile(
                        "mma.sync.aligned.m16n8k8.row.col.f32.tf32.tf32.f32 "
                        "{%0,%1,%2,%3}, {%4,%5,%6,%7}, {%8,%9}, {%0,%1,%2,%3};\n"
                        : "+f"(c[i][j][0]), "+f"(c[i][j][1]),
                          "+f"(c[i][j][2]), "+f"(c[i][j][3])
                        : "r"(a[i][0]), "r"(a[i][1]), "r"(a[i][2]), "r"(a[i][3]),
                          "r"(bf[j][0]), "r"(bf[j][1]));
                }
        }
    }

    // epilogue: bias add + store
    #pragma unroll
    for (int i = 0; i < 4; i++) {
        int row = m0 + wm + i * 16 + g;
        #pragma unroll
        for (int j = 0; j < 4; j++) {
            int ncol = wn + j * 8 + t4 * 2;
            float bx = bias[cb + ncol], bxx = bias[cb + ncol + 1];
            float2 v0 = make_float2(c[i][j][0] + bx, c[i][j][1] + bxx);
            float2 v1 = make_float2(c[i][j][2] + bx, c[i][j][3] + bxx);
            *(float2*)(C + (size_t)row * (2 * DD) + outc0 + ncol) = v0;
            *(float2*)(C + (size_t)(row + 8) * (2 * DD) + outc0 + ncol) = v1;
        }
    }
}

// ---------------- Small GEMM: C = scale*(A@op(B)) + bias, opt relu ----------------
// 32x64x32 tiles, 256 threads, 2x4 per thread. M must be multiple of 32 (352=11*32),
// N multiple of 64, K multiple of 32 -> no bounds checks.
// blockIdx.z selects between two (A,B,bias,C) sets so paired GEMMs share a launch.
__global__ void __launch_bounds__(256) gemm_small_kernel(
    const float* __restrict__ A0, const float* __restrict__ A1,
    const float* __restrict__ B0, const float* __restrict__ B1,
    const float* __restrict__ bias0, const float* __restrict__ bias1,
    float* __restrict__ C0, float* __restrict__ C1,
    int N, int K, int transB, float scale, int relu)
{
    const float* A = blockIdx.z ? A1 : A0;
    const float* Bm = blockIdx.z ? B1 : B0;
    const float* bias = blockIdx.z ? bias1 : bias0;
    float* C = blockIdx.z ? C1 : C0;

    __shared__ __align__(16) float As[32][36];
    __shared__ __align__(16) float Bs[32][68];
    int m0 = blockIdx.x * 32, n0 = blockIdx.y * 64;
    int t = threadIdx.x;
    int tx = t & 15, ty = t >> 4;
    float acc[2][4];
    #pragma unroll
    for (int i = 0; i < 2; i++)
        #pragma unroll
        for (int j = 0; j < 4; j++) acc[i][j] = 0.f;

    for (int k0 = 0; k0 < K; k0 += 32) {
        #pragma unroll
        for (int i = 0; i < 4; i++) {
            int idx = t + i * 256;
            int m = idx >> 5, k = idx & 31;
            As[k][m] = A[(size_t)(m0 + m) * K + k0 + k];
        }
        if (!transB) {
            #pragma unroll
            for (int i = 0; i < 8; i++) {
                int idx = t + i * 256;
                int k = idx >> 6, n = idx & 63;
                Bs[k][n] = Bm[(size_t)(k0 + k) * N + n0 + n];
            }
        } else {
            #pragma unroll
            for (int i = 0; i < 8; i++) {
                int idx = t + i * 256;
                int n = idx >> 5, k = idx & 31;
                Bs[k][n] = Bm[(size_t)(n0 + n) * K + k0 + k];
            }
        }
        __syncthreads();
        #pragma unroll
        for (int kk = 0; kk < 32; kk++) {
            float2 a = *(const float2*)&As[kk][ty * 2];
            float4 b = *(const float4*)&Bs[kk][tx * 4];
            acc[0][0] = fmaf(a.x, b.x, acc[0][0]);
            acc[0][1] = fmaf(a.x, b.y, acc[0][1]);
            acc[0][2] = fmaf(a.x, b.z, acc[0][2]);
            acc[0][3] = fmaf(a.x, b.w, acc[0][3]);
            acc[1][0] = fmaf(a.y, b.x, acc[1][0]);
            acc[1][1] = fmaf(a.y, b.y, acc[1][1]);
            acc[1][2] = fmaf(a.y, b.z, acc[1][2]);
            acc[1][3] = fmaf(a.y, b.w, acc[1][3]);
        }
        __syncthreads();
    }
    float4 bvv = make_float4(0.f, 0.f, 0.f, 0.f);
    if (bias) bvv = *(const float4*)(bias + n0 + tx * 4);
    #pragma unroll
    for (int i = 0; i < 2; i++) {
        int m = m0 + ty * 2 + i;
        float4 v;
        v.x = acc[i][0] * scale + bvv.x;
        v.y = acc[i][1] * scale + bvv.y;
        v.z = acc[i][2] * scale + bvv.z;
        v.w = acc[i][3] * scale + bvv.w;
        if (relu) {
            v.x = fmaxf(v.x, 0.f); v.y = fmaxf(v.y, 0.f);
            v.z = fmaxf(v.z, 0.f); v.w = fmaxf(v.w, 0.f);
        }
        *(float4*)(C + (size_t)m * N + n0 + tx * 4) = v;
    }
}

// ---------------- Fused logits + softmax(over S) + renorm partials ----------------
__global__ void __launch_bounds__(256) logits_softmax_kernel(
    const float* __restrict__ q, const float* __restrict__ kv,
    float* __restrict__ attn, float* __restrict__ lpart)
{
    int b = blockIdx.x, chunk = blockIdx.y;
    __shared__ __align__(16) float Qs[16 * 20];
    __shared__ __align__(16) float Ks[16 * 260];
    int t = threadIdx.x;
    int tx = t & 63, sg = t >> 6;
    int n0 = chunk * 256;
    const float* kb = kv + ((size_t)b * NN + n0) * (2 * DD);

    float acc[4][4];
    #pragma unroll
    for (int i = 0; i < 4; i++)
        #pragma unroll
        for (int j = 0; j < 4; j++) acc[i][j] = 0.f;

    for (int k0 = 0; k0 < DD; k0 += 16) {
        {
            int k = t & 15, s = t >> 4;
            Qs[k * 20 + s] = (s < SS) ? q[((size_t)(b * SS + s)) * DD + k0 + k] : 0.f;
        }
        #pragma unroll
        for (int i = 0; i < 4; i++) {
            int idx4 = t + i * 256;
            int n = idx4 >> 2, k4 = idx4 & 3;
            float4 v = *(const float4*)(kb + (size_t)n * (2 * DD) + k0 + k4 * 4);
            Ks[(k4 * 4 + 0) * 260 + n] = v.x;
            Ks[(k4 * 4 + 1) * 260 + n] = v.y;
            Ks[(k4 * 4 + 2) * 260 + n] = v.z;
            Ks[(k4 * 4 + 3) * 260 + n] = v.w;
        }
        __syncthreads();
        #pragma unroll
        for (int kk = 0; kk < 16; kk++) {
            float qv[4], kvv[4];
            *(float4*)qv  = *(const float4*)&Qs[kk * 20 + sg * 4];
            *(float4*)kvv = *(const float4*)&Ks[kk * 260 + tx * 4];
            #pragma unroll
            for (int i = 0; i < 4; i++)
                #pragma unroll
                for (int j = 0; j < 4; j++)
                    acc[i][j] = fmaf(qv[i], kvv[j], acc[i][j]);
        }
        __syncthreads();
    }

    #pragma unroll
    for (int i = 0; i < 4; i++)
        #pragma unroll
        for (int j = 0; j < 4; j++)
            Ks[(sg * 4 + i) * 260 + tx * 4 + j] = acc[i][j];
    __syncthreads();

    float p[SS];
    {
        int n = t;
        float m = -1e30f;
        #pragma unroll
        for (int s = 0; s < SS; s++) m = fmaxf(m, Ks[s * 260 + n]);
        float sum = 0.f;
        #pragma unroll
        for (int s = 0; s < SS; s++) { float e = __expf(Ks[s * 260 + n] - m); p[s] = e; sum += e; }
        float r = 1.f / sum;
        float* ar = attn + ((size_t)b * NN + n0 + n) * 16;
        #pragma unroll
        for (int s = 0; s < SS; s++) { p[s] *= r; ar[s] = p[s]; }
    }
    __syncthreads();
    #pragma unroll
    for (int s = 0; s < SS; s++) Ks[s * 260 + t] = p[s];
    __syncthreads();

    int w = t >> 5, lane = t & 31;
    for (int s = w; s < SS; s += 8) {
        float v = 0.f;
        #pragma unroll
        for (int i = 0; i < 8; i++) v += Ks[s * 260 + lane + i * 32];
        #pragma unroll
        for (int o = 16; o; o >>= 1) v += __shfl_xor_sync(0xffffffffu, v, o);
        if (lane == 0) lpart[(b * NCHUNK + chunk) * 16 + s] = v;
    }
}

// ---------------- inv = 1/(sum_n attn + eps) ----------------
__global__ void inv_kernel(const float* __restrict__ lpart, float* __restrict__ inv)
{
    int t = threadIdx.x;
    if (t < SROWS) {
        int b = t / SS, s = t % SS;
        float sum = 0.f;
        #pragma unroll
        for (int c = 0; c < NCHUNK; c++) sum += lpart[(b * NCHUNK + c) * 16 + s];
        inv[t] = 1.f / (sum + EPS_ATTN);
    }
}

// ---------------- updates partials ----------------
__device__ __forceinline__ void fma4(float4& a, float s, float4 v) {
    a.x = fmaf(s, v.x, a.x); a.y = fmaf(s, v.y, a.y);
    a.z = fmaf(s, v.z, a.z); a.w = fmaf(s, v.w, a.w);
}

__global__ void __launch_bounds__(128) updates_kernel(
    const float* __restrict__ kv, const float* __restrict__ attn,
    float* __restrict__ upart)
{
    int b = blockIdx.x, chunk = blockIdx.y, t = threadIdx.x;
    float4 acc[SS];
    #pragma unroll
    for (int s = 0; s < SS; s++) acc[s] = make_float4(0.f, 0.f, 0.f, 0.f);
    const float* vb = kv + (size_t)b * NN * (2 * DD) + DD;
    const float* pb = attn + (size_t)b * NN * 16;
    int n0 = chunk * 256;
    for (int n = n0; n < n0 + 256; n++) {
        float4 v = *(const float4*)(vb + (size_t)n * (2 * DD) + t * 4);
        const float* pr = pb + (size_t)n * 16;
        float4 p0 = *(const float4*)(pr);
        float4 p1 = *(const float4*)(pr + 4);
        float4 p2 = *(const float4*)(pr + 8);
        fma4(acc[0],  p0.x, v); fma4(acc[1],  p0.y, v);
        fma4(acc[2],  p0.z, v); fma4(acc[3],  p0.w, v);
        fma4(acc[4],  p1.x, v); fma4(acc[5],  p1.y, v);
        fma4(acc[6],  p1.z, v); fma4(acc[7],  p1.w, v);
        fma4(acc[8],  p2.x, v); fma4(acc[9],  p2.y, v);
        fma4(acc[10], p2.z, v);
    }
    #pragma unroll
    for (int s = 0; s < SS; s++)
        *(float4*)(upart + ((size_t)((b * NCHUNK + chunk) * SS + s)) * DD + t * 4) = acc[s];
}

// ---------------- reduce partials + apply renorm ----------------
__global__ void __launch_bounds__(128) upd_reduce_kernel(
    const float* __restrict__ upart, const float* __restrict__ inv,
    float* __restrict__ upd)
{
    int row = blockIdx.x;
    int b = row / SS, s = row % SS;
    int t = threadIdx.x;
    float4 acc = make_float4(0.f, 0.f, 0.f, 0.f);
    for (int c = 0; c < NCHUNK; c++) {
        float4 v = *(const float4*)(upart + ((size_t)((b * NCHUNK + c) * SS + s)) * DD + t * 4);
        acc.x += v.x; acc.y += v.y; acc.z += v.z; acc.w += v.w;
    }
    float iv = inv[row];
    acc.x *= iv; acc.y *= iv; acc.z *= iv; acc.w *= iv;
    *(float4*)(upd + (size_t)row * DD + t * 4) = acc;
}

// ---------------- GRU elementwise ----------------
__global__ void __launch_bounds__(256) gru_kernel(
    const float* __restrict__ gi, const float* __restrict__ gh,
    const float* __restrict__ slots, float* __restrict__ out)
{
    int idx = blockIdx.x * 256 + threadIdx.x;
    if (idx >= SROWS * DD) return;
    int row = idx >> 9, d = idx & 511;
    size_t base = (size_t)row * (3 * DD);
    float ir = gi[base + d], iz = gi[base + DD + d], inn = gi[base + 2 * DD + d];
    float hr = gh[base + d], hz = gh[base + DD + d], hn = gh[base + 2 * DD + d];
    float r = 1.f / (1.f + __expf(-(ir + hr)));
    float z = 1.f / (1.f + __expf(-(iz + hz)));
    float nn = tanhf(inn + r * hn);
    out[idx] = (1.f - z) * nn + z * slots[idx];
}

// ---------------- Host orchestration ----------------
extern "C" void kernel_launch(void* const* d_in, const int* in_sizes, int n_in,
                              void* d_out, int out_size)
{
    const float* slots0  = (const float*)d_in[0];
    const float* inputs  = (const float*)d_in[1];
    const float* ln_in_g = (const float*)d_in[2];
    const float* ln_in_b = (const float*)d_in[3];
    const float* Wk      = (const float*)d_in[4];
    const float* bk      = (const float*)d_in[5];
    const float* Wv      = (const float*)d_in[6];
    const float* bv      = (const float*)d_in[7];
    const float* ln_q_g  = (const float*)d_in[8];
    const float* ln_q_b  = (const float*)d_in[9];
    const float* Wq      = (const float*)d_in[10];
    const float* W_ih    = (const float*)d_in[11];
    const float* b_ih    = (const float*)d_in[12];
    const float* W_hh    = (const float*)d_in[13];
    const float* b_hh    = (const float*)d_in[14];
    const float* ln_m_g  = (const float*)d_in[15];
    const float* ln_m_b  = (const float*)d_in[16];
    const float* W1      = (const float*)d_in[17];
    const float* b1      = (const float*)d_in[18];
    const float* W2      = (const float*)d_in[19];
    const float* b2      = (const float*)d_in[20];
    float* out = (float*)d_out;

    float *xln, *kvp, *qp, *attn, *lpart, *invp, *upart, *upd, *gi, *gh;
    float *stmp, *sA, *sB, *lnb, *h1;
    cudaGetSymbolAddress((void**)&xln,  g_xln);
    cudaGetSymbolAddress((void**)&kvp,  g_kv);
    cudaGetSymbolAddress((void**)&qp,   g_q);
    cudaGetSymbolAddress((void**)&attn, g_attn);
    cudaGetSymbolAddress((void**)&lpart,g_lpart);
    cudaGetSymbolAddress((void**)&invp, g_inv);
    cudaGetSymbolAddress((void**)&upart,g_upart);
    cudaGetSymbolAddress((void**)&upd,  g_upd);
    cudaGetSymbolAddress((void**)&gi,   g_gi);
    cudaGetSymbolAddress((void**)&gh,   g_gh);
    cudaGetSymbolAddress((void**)&stmp, g_stmp);
    cudaGetSymbolAddress((void**)&sA,   g_sA);
    cudaGetSymbolAddress((void**)&sB,   g_sB);
    cudaGetSymbolAddress((void**)&lnb,  g_lnb);
    cudaGetSymbolAddress((void**)&h1,   g_h1);

    const float qscale = 0.044194173824159216f; // 1/sqrt(512)

    // one-time: input LN + k/v projections (tf32 tensor cores)
    rowln_kernel<<<MROWS, 256>>>(inputs, ln_in_g, ln_in_b, xln);
    kv_gemm_tf32_kernel<<<dim3(MROWS / 128, 8), 256>>>(xln, Wk, Wv, bk, bv, kvp);

    const float* cur = slots0;
    for (int it = 0; it < 3; it++) {
        // q = LN(slots) @ Wq * scale
        rowln_kernel<<<SROWS, 256>>>(cur, ln_q_g, ln_q_b, lnb);
        gemm_small_kernel<<<dim3(11, 8, 1), 256>>>(
            lnb, lnb, Wq, Wq, nullptr, nullptr, qp, qp,
            DD, DD, 0, qscale, 0);
        // inverted attention
        logits_softmax_kernel<<<dim3(BB, NCHUNK), 256>>>(qp, kvp, attn, lpart);
        inv_kernel<<<1, 384>>>(lpart, invp);
        updates_kernel<<<dim3(BB, NCHUNK), 128>>>(kvp, attn, upart);
        upd_reduce_kernel<<<SROWS, 128>>>(upart, invp, upd);
        // GRU gates: gi = upd @ W_ih^T + b_ih ; gh = cur @ W_hh^T + b_hh (one launch)
        gemm_small_kernel<<<dim3(11, 24, 2), 256>>>(
            upd, cur, W_ih, W_hh, b_ih, b_hh, gi, gh,
            3 * DD, DD, 1, 1.f, 0);
        gru_kernel<<<(SROWS * DD + 255) / 256, 256>>>(gi, gh, cur, stmp);
        // MLP (no residual)
        rowln_kernel<<<SROWS, 256>>>(stmp, ln_m_g, ln_m_b, lnb);
        gemm_small_kernel<<<dim3(11, 32, 1), 256>>>(
            lnb, lnb, W1, W1, b1, b1, h1, h1,
            MLPD, DD, 0, 1.f, 1);
        float* nxt = (it == 2) ? out : (it == 0 ? sA : sB);
        gemm_small_kernel<<<dim3(11, 8, 1), 256>>>(
            h1, h1, W2, W2, b2, b2, nxt, nxt,
            DD, MLPD, 0, 1.f, 0);
        cur = nxt;
    }
}

// round 9
// speedup vs baseline: 3.0856x; 1.3379x over previous
#include <cuda_runtime.h>
#include <cuda_bf16.h>
#include <math.h>
#include <stdint.h>

// ---------------- Problem constants ----------------
#define BB 32
#define SS 11
#define NN 4096
#define DD 512
#define MLPD 2048
#define MROWS (BB*NN)          // 131072
#define SROWS (BB*SS)          // 352
#define NCHUNK 16              // n-chunks per batch (4096/256)
#define EPS_LN 1e-5f
#define EPS_ATTN 1e-8f

// ---------------- Scratch (device globals; no allocation allowed) ----------------
__device__ __nv_bfloat16 g_xlnb[MROWS*DD];   // 128 MB normalized inputs (bf16)
__device__ __nv_bfloat16 g_kb[MROWS*DD];     // 128 MB K (bf16)
__device__ __nv_bfloat16 g_vb[MROWS*DD];     // 128 MB V (bf16)
__device__ __nv_bfloat16 g_wkb[DD*DD];       // Wk transposed [n][k] bf16
__device__ __nv_bfloat16 g_wvb[DD*DD];       // Wv transposed [n][k] bf16
__device__ float g_q[SROWS*DD];
__device__ float g_attn[BB*NN*16];           // softmax probs, s-padded to 16
__device__ float g_lpart[BB*NCHUNK*16];
__device__ float g_inv[SROWS];
__device__ float g_upart[BB*NCHUNK*SS*DD];
__device__ float g_upd[SROWS*DD];
__device__ float g_gi[SROWS*3*DD];
__device__ float g_gh[SROWS*3*DD];
__device__ float g_stmp[SROWS*DD];
__device__ float g_sA[SROWS*DD];
__device__ float g_sB[SROWS*DD];
__device__ float g_lnb[SROWS*DD];
__device__ float g_h1[SROWS*MLPD];

// ---------------- W transpose + bf16 convert (one-time, tiny) ----------------
__global__ void wtrans_kernel(const float* __restrict__ Wk, const float* __restrict__ Wv,
                              __nv_bfloat16* __restrict__ Ko, __nv_bfloat16* __restrict__ Vo)
{
    __shared__ float tile[32][33];
    const float* src = blockIdx.z ? Wv : Wk;
    __nv_bfloat16* dst = blockIdx.z ? Vo : Ko;
    int k0 = blockIdx.x * 32, n0 = blockIdx.y * 32;
    int tx = threadIdx.x, ty = threadIdx.y;
    tile[ty][tx] = src[(size_t)(k0 + ty) * DD + n0 + tx];
    __syncthreads();
    dst[(size_t)(n0 + ty) * DD + k0 + tx] = __float2bfloat16(tile[tx][ty]);
}

// ---------------- Row LayerNorm -> bf16 out (for inputs) ----------------
__global__ void __launch_bounds__(256) rowln_bf16_kernel(
    const float* __restrict__ X, const float* __restrict__ g,
    const float* __restrict__ b, __nv_bfloat16* __restrict__ out)
{
    int row = blockIdx.x;
    int t = threadIdx.x;
    const float* x = X + (size_t)row * DD;
    float2 v = *(const float2*)(x + 2 * t);
    float s = v.x + v.y;
    float sq = v.x * v.x + v.y * v.y;
    int w = t >> 5, lane = t & 31;
    #pragma unroll
    for (int o = 16; o; o >>= 1) {
        s  += __shfl_xor_sync(0xffffffffu, s, o);
        sq += __shfl_xor_sync(0xffffffffu, sq, o);
    }
    __shared__ float shs[8], shq[8];
    __shared__ float mu_s, rs_s;
    if (lane == 0) { shs[w] = s; shq[w] = sq; }
    __syncthreads();
    if (t == 0) {
        float S = 0.f, Q = 0.f;
        #pragma unroll
        for (int i = 0; i < 8; i++) { S += shs[i]; Q += shq[i]; }
        float mu = S * (1.f / DD);
        float var = Q * (1.f / DD) - mu * mu;
        mu_s = mu;
        rs_s = rsqrtf(var + EPS_LN);
    }
    __syncthreads();
    float mu = mu_s, rs = rs_s;
    float2 gg = *(const float2*)(g + 2 * t);
    float2 bb = *(const float2*)(b + 2 * t);
    float o0 = (v.x - mu) * rs * gg.x + bb.x;
    float o1 = (v.y - mu) * rs * gg.y + bb.y;
    *(__nv_bfloat162*)(out + (size_t)row * DD + 2 * t) = __floats2bfloat162_rn(o0, o1);
}

// ---------------- Row LayerNorm fp32 (for slots; rows of 512) ----------------
__global__ void __launch_bounds__(256) rowln_kernel(
    const float* __restrict__ X, const float* __restrict__ g,
    const float* __restrict__ b, float* __restrict__ out)
{
    int row = blockIdx.x;
    int t = threadIdx.x;
    const float* x = X + (size_t)row * DD;
    float v0 = x[t], v1 = x[t + 256];
    float s = v0 + v1;
    float sq = v0 * v0 + v1 * v1;
    int w = t >> 5, lane = t & 31;
    #pragma unroll
    for (int o = 16; o; o >>= 1) {
        s  += __shfl_xor_sync(0xffffffffu, s, o);
        sq += __shfl_xor_sync(0xffffffffu, sq, o);
    }
    __shared__ float shs[8], shq[8];
    __shared__ float mu_s, rs_s;
    if (lane == 0) { shs[w] = s; shq[w] = sq; }
    __syncthreads();
    if (t == 0) {
        float S = 0.f, Q = 0.f;
        #pragma unroll
        for (int i = 0; i < 8; i++) { S += shs[i]; Q += shq[i]; }
        float mu = S * (1.f / DD);
        float var = Q * (1.f / DD) - mu * mu;
        mu_s = mu;
        rs_s = rsqrtf(var + EPS_LN);
    }
    __syncthreads();
    float mu = mu_s, rs = rs_s;
    float* o = out + (size_t)row * DD;
    o[t]       = (v0 - mu) * rs * g[t]       + b[t];
    o[t + 256] = (v1 - mu) * rs * g[t + 256] + b[t + 256];
}

// ---------------- bf16 tensor-core GEMM: K|V = xlnb @ W^T(+bias), bf16 out --------
// 128x128 block tile, BK=32, 256 threads (8 warps: 2m x 4n, warp tile 64x32).
// mma.sync.m16n8k16 bf16, fp32 accumulate. A: g_xlnb [m][k] bf16, B: g_w?b [n][k] bf16.
// grid = (8, 1024): blockIdx.x = column-block (0-3 -> K, 4-7 -> V) so consecutive
// CTAs reuse the same A tile from L2.
__global__ void __launch_bounds__(256) kv_gemm_bf16_kernel(
    const __nv_bfloat16* __restrict__ A,
    const __nv_bfloat16* __restrict__ Wkb, const __nv_bfloat16* __restrict__ Wvb,
    const float* __restrict__ bk, const float* __restrict__ bv,
    __nv_bfloat16* __restrict__ Kout, __nv_bfloat16* __restrict__ Vout)
{
    __shared__ uint32_t As32[128][20];   // [m][k2], stride 20 -> conflict-free frags
    __shared__ uint32_t Bs32[128][20];   // [n][k2]
    int by = blockIdx.x;                 // 0..7
    int m0 = blockIdx.y * 128;
    const __nv_bfloat16* W; const float* bias; __nv_bfloat16* Dst; int cb;
    if (by < 4) { W = Wkb; bias = bk; Dst = Kout; cb = by * 128; }
    else        { W = Wvb; bias = bv; Dst = Vout; cb = (by - 4) * 128; }

    int t = threadIdx.x;
    int warp = t >> 5, lane = t & 31;
    int wm = (warp & 1) * 64;
    int wn = (warp >> 1) * 32;
    int g = lane >> 2, t4 = lane & 3;

    const uint4* A4 = (const uint4*)A;       // 64 uint4 per 512-col row
    const uint4* W4 = (const uint4*)W;

    float c[4][4][4];
    #pragma unroll
    for (int i = 0; i < 4; i++)
        #pragma unroll
        for (int j = 0; j < 4; j++)
            #pragma unroll
            for (int r = 0; r < 4; r++) c[i][j][r] = 0.f;

    for (int k0 = 0; k0 < DD; k0 += 32) {
        // prefetch: A tile 128x32 bf16 = 512 uint4; B same. 2 uint4 each per array.
        uint4 av[2], bw[2];
        int am[2], aq[2], bn[2], bq[2];
        #pragma unroll
        for (int i = 0; i < 2; i++) {
            int item = t + i * 256;
            am[i] = item >> 2; aq[i] = item & 3;
            av[i] = A4[(size_t)(m0 + am[i]) * 64 + (k0 >> 3) + aq[i]];
            bn[i] = item >> 2; bq[i] = item & 3;
            bw[i] = W4[(size_t)(cb + bn[i]) * 64 + (k0 >> 3) + bq[i]];
        }
        __syncthreads();   // previous compute done
        #pragma unroll
        for (int i = 0; i < 2; i++) {
            const uint32_t* ap = (const uint32_t*)&av[i];
            const uint32_t* bp = (const uint32_t*)&bw[i];
            #pragma unroll
            for (int jj = 0; jj < 4; jj++) {
                As32[am[i]][aq[i] * 4 + jj] = ap[jj];
                Bs32[bn[i]][bq[i] * 4 + jj] = bp[jj];
            }
        }
        __syncthreads();

        #pragma unroll
        for (int ks = 0; ks < 2; ks++) {
            int kb2 = ks * 8;
            uint32_t a[4][4], bf[4][2];
            #pragma unroll
            for (int i = 0; i < 4; i++) {
                int mb = wm + i * 16;
                a[i][0] = As32[mb + g][kb2 + t4];
                a[i][1] = As32[mb + g + 8][kb2 + t4];
                a[i][2] = As32[mb + g][kb2 + t4 + 4];
                a[i][3] = As32[mb + g + 8][kb2 + t4 + 4];
            }
            #pragma unroll
            for (int j = 0; j < 4; j++) {
                int nb = wn + j * 8;
                bf[j][0] = Bs32[nb + g][kb2 + t4];
                bf[j][1] = Bs32[nb + g][kb2 + t4 + 4];
            }
            #pragma unroll
            for (int i = 0; i < 4; i++)
                #pragma unroll
                for (int j = 0; j < 4; j++) {
                    asm volatile(
                        "mma.sync.aligned.m16n8k16.row.col.f32.bf16.bf16.f32 "
                        "{%0,%1,%2,%3}, {%4,%5,%6,%7}, {%8,%9}, {%0,%1,%2,%3};\n"
                        : "+f"(c[i][j][0]), "+f"(c[i][j][1]),
                          "+f"(c[i][j][2]), "+f"(c[i][j][3])
                        : "r"(a[i][0]), "r"(a[i][1]), "r"(a[i][2]), "r"(a[i][3]),
                          "r"(bf[j][0]), "r"(bf[j][1]));
                }
        }
    }

    // epilogue: bias add, convert bf16x2, store. Dst row stride 512 bf16 = 256 u32.
    uint32_t* D32 = (uint32_t*)Dst;
    #pragma unroll
    for (int i = 0; i < 4; i++) {
        int row = m0 + wm + i * 16 + g;
        #pragma unroll
        for (int j = 0; j < 4; j++) {
            int col = wn + j * 8 + t4 * 2;           // within 128-wide tile
            float bx = bias[cb + col], by2 = bias[cb + col + 1];
            int c2 = ((cb + col) >> 1);
            __nv_bfloat162 v0 = __floats2bfloat162_rn(c[i][j][0] + bx, c[i][j][1] + by2);
            __nv_bfloat162 v1 = __floats2bfloat162_rn(c[i][j][2] + bx, c[i][j][3] + by2);
            D32[(size_t)row * 256 + c2] = *(uint32_t*)&v0;
            D32[(size_t)(row + 8) * 256 + c2] = *(uint32_t*)&v1;
        }
    }
}

// ---------------- Small GEMM: C = scale*(A@op(B)) + bias, opt relu ----------------
// 16x64x32 tiles, 128 threads, 2x4 per thread. M mult of 16 (352), N mult of 64,
// K mult of 32. blockIdx.z selects between two (A,B,bias,C) sets.
__global__ void __launch_bounds__(128) gemm_small_kernel(
    const float* __restrict__ A0, const float* __restrict__ A1,
    const float* __restrict__ B0, const float* __restrict__ B1,
    const float* __restrict__ bias0, const float* __restrict__ bias1,
    float* __restrict__ C0, float* __restrict__ C1,
    int N, int K, int transB, float scale, int relu)
{
    const float* A = blockIdx.z ? A1 : A0;
    const float* Bm = blockIdx.z ? B1 : B0;
    const float* bias = blockIdx.z ? bias1 : bias0;
    float* C = blockIdx.z ? C1 : C0;

    __shared__ __align__(16) float As[32][18];
    __shared__ __align__(16) float Bs[32][68];
    int m0 = blockIdx.x * 16, n0 = blockIdx.y * 64;
    int t = threadIdx.x;
    int tx = t & 15, ty = t >> 4;
    float acc[2][4];
    #pragma unroll
    for (int i = 0; i < 2; i++)
        #pragma unroll
        for (int j = 0; j < 4; j++) acc[i][j] = 0.f;

    for (int k0 = 0; k0 < K; k0 += 32) {
        #pragma unroll
        for (int i = 0; i < 4; i++) {
            int idx = t + i * 128;
            int m = idx >> 5, k = idx & 31;
            As[k][m] = A[(size_t)(m0 + m) * K + k0 + k];
        }
        if (!transB) {
            #pragma unroll
            for (int i = 0; i < 16; i++) {
                int idx = t + i * 128;
                int k = idx >> 6, n = idx & 63;
                Bs[k][n] = Bm[(size_t)(k0 + k) * N + n0 + n];
            }
        } else {
            #pragma unroll
            for (int i = 0; i < 16; i++) {
                int idx = t + i * 128;
                int n = idx >> 5, k = idx & 31;
                Bs[k][n] = Bm[(size_t)(n0 + n) * K + k0 + k];
            }
        }
        __syncthreads();
        #pragma unroll
        for (int kk = 0; kk < 32; kk++) {
            float a0 = As[kk][ty * 2], a1 = As[kk][ty * 2 + 1];
            float4 b = *(const float4*)&Bs[kk][tx * 4];
            acc[0][0] = fmaf(a0, b.x, acc[0][0]);
            acc[0][1] = fmaf(a0, b.y, acc[0][1]);
            acc[0][2] = fmaf(a0, b.z, acc[0][2]);
            acc[0][3] = fmaf(a0, b.w, acc[0][3]);
            acc[1][0] = fmaf(a1, b.x, acc[1][0]);
            acc[1][1] = fmaf(a1, b.y, acc[1][1]);
            acc[1][2] = fmaf(a1, b.z, acc[1][2]);
            acc[1][3] = fmaf(a1, b.w, acc[1][3]);
        }
        __syncthreads();
    }
    float4 bvv = make_float4(0.f, 0.f, 0.f, 0.f);
    if (bias) bvv = *(const float4*)(bias + n0 + tx * 4);
    #pragma unroll
    for (int i = 0; i < 2; i++) {
        int m = m0 + ty * 2 + i;
        float4 v;
        v.x = acc[i][0] * scale + bvv.x;
        v.y = acc[i][1] * scale + bvv.y;
        v.z = acc[i][2] * scale + bvv.z;
        v.w = acc[i][3] * scale + bvv.w;
        if (relu) {
            v.x = fmaxf(v.x, 0.f); v.y = fmaxf(v.y, 0.f);
            v.z = fmaxf(v.z, 0.f); v.w = fmaxf(v.w, 0.f);
        }
        *(float4*)(C + (size_t)m * N + n0 + tx * 4) = v;
    }
}

// ---------------- Fused logits + softmax(over S) + renorm partials ----------------
// K now bf16 (separate array, row stride 512).
__global__ void __launch_bounds__(256) logits_softmax_kernel(
    const float* __restrict__ q, const __nv_bfloat16* __restrict__ Kb,
    float* __restrict__ attn, float* __restrict__ lpart)
{
    int b = blockIdx.x, chunk = blockIdx.y;
    __shared__ __align__(16) float Qs[16 * 20];
    __shared__ __align__(16) float Ks[16 * 260];
    int t = threadIdx.x;
    int tx = t & 63, sg = t >> 6;
    int n0 = chunk * 256;
    const uint4* kb4 = (const uint4*)(Kb + ((size_t)b * NN + n0) * DD);  // 64 u4/row

    float acc[4][4];
    #pragma unroll
    for (int i = 0; i < 4; i++)
        #pragma unroll
        for (int j = 0; j < 4; j++) acc[i][j] = 0.f;

    for (int k0 = 0; k0 < DD; k0 += 16) {
        {
            int k = t & 15, s = t >> 4;
            Qs[k * 20 + s] = (s < SS) ? q[((size_t)(b * SS + s)) * DD + k0 + k] : 0.f;
        }
        // K chunk: 256n x 16k bf16 = 512 uint4, 2 per thread
        #pragma unroll
        for (int i = 0; i < 2; i++) {
            int item = t + i * 256;
            int n = item >> 1, h = item & 1;
            uint4 gl = kb4[(size_t)n * 64 + (k0 >> 3) + h];
            const __nv_bfloat162* hp = (const __nv_bfloat162*)&gl;
            #pragma unroll
            for (int p = 0; p < 4; p++) {
                float2 f = __bfloat1622float2(hp[p]);
                Ks[(h * 8 + 2 * p) * 260 + n] = f.x;
                Ks[(h * 8 + 2 * p + 1) * 260 + n] = f.y;
            }
        }
        __syncthreads();
        #pragma unroll
        for (int kk = 0; kk < 16; kk++) {
            float qv[4], kvv[4];
            *(float4*)qv  = *(const float4*)&Qs[kk * 20 + sg * 4];
            *(float4*)kvv = *(const float4*)&Ks[kk * 260 + tx * 4];
            #pragma unroll
            for (int i = 0; i < 4; i++)
                #pragma unroll
                for (int j = 0; j < 4; j++)
                    acc[i][j] = fmaf(qv[i], kvv[j], acc[i][j]);
        }
        __syncthreads();
    }

    #pragma unroll
    for (int i = 0; i < 4; i++)
        #pragma unroll
        for (int j = 0; j < 4; j++)
            Ks[(sg * 4 + i) * 260 + tx * 4 + j] = acc[i][j];
    __syncthreads();

    float p[SS];
    {
        int n = t;
        float m = -1e30f;
        #pragma unroll
        for (int s = 0; s < SS; s++) m = fmaxf(m, Ks[s * 260 + n]);
        float sum = 0.f;
        #pragma unroll
        for (int s = 0; s < SS; s++) { float e = __expf(Ks[s * 260 + n] - m); p[s] = e; sum += e; }
        float r = 1.f / sum;
        float* ar = attn + ((size_t)b * NN + n0 + n) * 16;
        #pragma unroll
        for (int s = 0; s < SS; s++) { p[s] *= r; ar[s] = p[s]; }
    }
    __syncthreads();
    #pragma unroll
    for (int s = 0; s < SS; s++) Ks[s * 260 + t] = p[s];
    __syncthreads();

    int w = t >> 5, lane = t & 31;
    for (int s = w; s < SS; s += 8) {
        float v = 0.f;
        #pragma unroll
        for (int i = 0; i < 8; i++) v += Ks[s * 260 + lane + i * 32];
        #pragma unroll
        for (int o = 16; o; o >>= 1) v += __shfl_xor_sync(0xffffffffu, v, o);
        if (lane == 0) lpart[(b * NCHUNK + chunk) * 16 + s] = v;
    }
}

// ---------------- inv = 1/(sum_n attn + eps) ----------------
__global__ void inv_kernel(const float* __restrict__ lpart, float* __restrict__ inv)
{
    int t = threadIdx.x;
    if (t < SROWS) {
        int b = t / SS, s = t % SS;
        float sum = 0.f;
        #pragma unroll
        for (int c = 0; c < NCHUNK; c++) sum += lpart[(b * NCHUNK + c) * 16 + s];
        inv[t] = 1.f / (sum + EPS_ATTN);
    }
}

// ---------------- updates partials (V bf16) ----------------
__device__ __forceinline__ void fma4(float4& a, float s, float4 v) {
    a.x = fmaf(s, v.x, a.x); a.y = fmaf(s, v.y, a.y);
    a.z = fmaf(s, v.z, a.z); a.w = fmaf(s, v.w, a.w);
}

__global__ void __launch_bounds__(128) updates_kernel(
    const __nv_bfloat16* __restrict__ Vb, const float* __restrict__ attn,
    float* __restrict__ upart)
{
    int b = blockIdx.x, chunk = blockIdx.y, t = threadIdx.x;
    float4 acc[SS];
    #pragma unroll
    for (int s = 0; s < SS; s++) acc[s] = make_float4(0.f, 0.f, 0.f, 0.f);
    const __nv_bfloat16* vb = Vb + (size_t)b * NN * DD;
    const float* pb = attn + (size_t)b * NN * 16;
    int n0 = chunk * 256;
    for (int n = n0; n < n0 + 256; n++) {
        uint2 raw = *(const uint2*)(vb + (size_t)n * DD + t * 4);
        __nv_bfloat162 h0 = *(__nv_bfloat162*)&raw.x;
        __nv_bfloat162 h1 = *(__nv_bfloat162*)&raw.y;
        float2 f0 = __bfloat1622float2(h0);
        float2 f1 = __bfloat1622float2(h1);
        float4 v = make_float4(f0.x, f0.y, f1.x, f1.y);
        const float* pr = pb + (size_t)n * 16;
        float4 p0 = *(const float4*)(pr);
        float4 p1 = *(const float4*)(pr + 4);
        float4 p2 = *(const float4*)(pr + 8);
        fma4(acc[0],  p0.x, v); fma4(acc[1],  p0.y, v);
        fma4(acc[2],  p0.z, v); fma4(acc[3],  p0.w, v);
        fma4(acc[4],  p1.x, v); fma4(acc[5],  p1.y, v);
        fma4(acc[6],  p1.z, v); fma4(acc[7],  p1.w, v);
        fma4(acc[8],  p2.x, v); fma4(acc[9],  p2.y, v);
        fma4(acc[10], p2.z, v);
    }
    #pragma unroll
    for (int s = 0; s < SS; s++)
        *(float4*)(upart + ((size_t)((b * NCHUNK + chunk) * SS + s)) * DD + t * 4) = acc[s];
}

// ---------------- reduce partials + apply renorm ----------------
__global__ void __launch_bounds__(128) upd_reduce_kernel(
    const float* __restrict__ upart, const float* __restrict__ inv,
    float* __restrict__ upd)
{
    int row = blockIdx.x;
    int b = row / SS, s = row % SS;
    int t = threadIdx.x;
    float4 acc = make_float4(0.f, 0.f, 0.f, 0.f);
    for (int c = 0; c < NCHUNK; c++) {
        float4 v = *(const float4*)(upart + ((size_t)((b * NCHUNK + c) * SS + s)) * DD + t * 4);
        acc.x += v.x; acc.y += v.y; acc.z += v.z; acc.w += v.w;
    }
    float iv = inv[row];
    acc.x *= iv; acc.y *= iv; acc.z *= iv; acc.w *= iv;
    *(float4*)(upd + (size_t)row * DD + t * 4) = acc;
}

// ---------------- GRU elementwise ----------------
__global__ void __launch_bounds__(256) gru_kernel(
    const float* __restrict__ gi, const float* __restrict__ gh,
    const float* __restrict__ slots, float* __restrict__ out)
{
    int idx = blockIdx.x * 256 + threadIdx.x;
    if (idx >= SROWS * DD) return;
    int row = idx >> 9, d = idx & 511;
    size_t base = (size_t)row * (3 * DD);
    float ir = gi[base + d], iz = gi[base + DD + d], inn = gi[base + 2 * DD + d];
    float hr = gh[base + d], hz = gh[base + DD + d], hn = gh[base + 2 * DD + d];
    float r = 1.f / (1.f + __expf(-(ir + hr)));
    float z = 1.f / (1.f + __expf(-(iz + hz)));
    float nn = tanhf(inn + r * hn);
    out[idx] = (1.f - z) * nn + z * slots[idx];
}

// ---------------- Host orchestration ----------------
extern "C" void kernel_launch(void* const* d_in, const int* in_sizes, int n_in,
                              void* d_out, int out_size)
{
    const float* slots0  = (const float*)d_in[0];
    const float* inputs  = (const float*)d_in[1];
    const float* ln_in_g = (const float*)d_in[2];
    const float* ln_in_b = (const float*)d_in[3];
    const float* Wk      = (const float*)d_in[4];
    const float* bk      = (const float*)d_in[5];
    const float* Wv      = (const float*)d_in[6];
    const float* bv      = (const float*)d_in[7];
    const float* ln_q_g  = (const float*)d_in[8];
    const float* ln_q_b  = (const float*)d_in[9];
    const float* Wq      = (const float*)d_in[10];
    const float* W_ih    = (const float*)d_in[11];
    const float* b_ih    = (const float*)d_in[12];
    const float* W_hh    = (const float*)d_in[13];
    const float* b_hh    = (const float*)d_in[14];
    const float* ln_m_g  = (const float*)d_in[15];
    const float* ln_m_b  = (const float*)d_in[16];
    const float* W1      = (const float*)d_in[17];
    const float* b1      = (const float*)d_in[18];
    const float* W2      = (const float*)d_in[19];
    const float* b2      = (const float*)d_in[20];
    float* out = (float*)d_out;

    __nv_bfloat16 *xlnb, *kb, *vb2, *wkb, *wvb;
    float *qp, *attn, *lpart, *invp, *upart, *upd, *gi, *gh;
    float *stmp, *sA, *sB, *lnb, *h1;
    cudaGetSymbolAddress((void**)&xlnb, g_xlnb);
    cudaGetSymbolAddress((void**)&kb,   g_kb);
    cudaGetSymbolAddress((void**)&vb2,  g_vb);
    cudaGetSymbolAddress((void**)&wkb,  g_wkb);
    cudaGetSymbolAddress((void**)&wvb,  g_wvb);
    cudaGetSymbolAddress((void**)&qp,   g_q);
    cudaGetSymbolAddress((void**)&attn, g_attn);
    cudaGetSymbolAddress((void**)&lpart,g_lpart);
    cudaGetSymbolAddress((void**)&invp, g_inv);
    cudaGetSymbolAddress((void**)&upart,g_upart);
    cudaGetSymbolAddress((void**)&upd,  g_upd);
    cudaGetSymbolAddress((void**)&gi,   g_gi);
    cudaGetSymbolAddress((void**)&gh,   g_gh);
    cudaGetSymbolAddress((void**)&stmp, g_stmp);
    cudaGetSymbolAddress((void**)&sA,   g_sA);
    cudaGetSymbolAddress((void**)&sB,   g_sB);
    cudaGetSymbolAddress((void**)&lnb,  g_lnb);
    cudaGetSymbolAddress((void**)&h1,   g_h1);

    const float qscale = 0.044194173824159216f; // 1/sqrt(512)

    // one-time: W transpose->bf16, input LN->bf16, kv GEMM (bf16 tensor cores)
    wtrans_kernel<<<dim3(16, 16, 2), dim3(32, 32)>>>(Wk, Wv, wkb, wvb);
    rowln_bf16_kernel<<<MROWS, 256>>>(inputs, ln_in_g, ln_in_b, xlnb);
    kv_gemm_bf16_kernel<<<dim3(8, MROWS / 128), 256>>>(xlnb, wkb, wvb, bk, bv, kb, vb2);

    const float* cur = slots0;
    for (int it = 0; it < 3; it++) {
        // q = LN(slots) @ Wq * scale
        rowln_kernel<<<SROWS, 256>>>(cur, ln_q_g, ln_q_b, lnb);
        gemm_small_kernel<<<dim3(22, 8, 1), 128>>>(
            lnb, lnb, Wq, Wq, nullptr, nullptr, qp, qp,
            DD, DD, 0, qscale, 0);
        // inverted attention
        logits_softmax_kernel<<<dim3(BB, NCHUNK), 256>>>(qp, kb, attn, lpart);
        inv_kernel<<<1, 384>>>(lpart, invp);
        updates_kernel<<<dim3(BB, NCHUNK), 128>>>(vb2, attn, upart);
        upd_reduce_kernel<<<SROWS, 128>>>(upart, invp, upd);
        // GRU gates (one launch for both)
        gemm_small_kernel<<<dim3(22, 24, 2), 128>>>(
            upd, cur, W_ih, W_hh, b_ih, b_hh, gi, gh,
            3 * DD, DD, 1, 1.f, 0);
        gru_kernel<<<(SROWS * DD + 255) / 256, 256>>>(gi, gh, cur, stmp);
        // MLP (no residual)
        rowln_kernel<<<SROWS, 256>>>(stmp, ln_m_g, ln_m_b, lnb);
        gemm_small_kernel<<<dim3(22, 32, 1), 128>>>(
            lnb, lnb, W1, W1, b1, b1, h1, h1,
            MLPD, DD, 0, 1.f, 1);
        float* nxt = (it == 2) ? out : (it == 0 ? sA : sB);
        gemm_small_kernel<<<dim3(22, 8, 1), 128>>>(
            h1, h1, W2, W2, b2, b2, nxt, nxt,
            DD, MLPD, 0, 1.f, 0);
        cur = nxt;
    }
}

// round 10
// speedup vs baseline: 3.6390x; 1.1793x over previous
#include <cuda_runtime.h>
#include <cuda_bf16.h>
#include <math.h>
#include <stdint.h>

// ---------------- Problem constants ----------------
#define BB 32
#define SS 11
#define NN 4096
#define DD 512
#define MLPD 2048
#define MROWS (BB*NN)          // 131072
#define SROWS (BB*SS)          // 352
#define NCHUNK 16              // n-chunks per batch (4096/256)
#define EPS_LN 1e-5f
#define EPS_ATTN 1e-8f

// ---------------- Scratch (device globals; no allocation allowed) ----------------
__device__ __nv_bfloat16 g_xlnb[MROWS*DD];   // 128 MB normalized inputs (bf16)
__device__ __nv_bfloat16 g_kb[MROWS*DD];     // 128 MB K (bf16)
__device__ __nv_bfloat16 g_vb[MROWS*DD];     // 128 MB V (bf16)
__device__ __nv_bfloat16 g_wkb[DD*DD];       // Wk transposed [n][k] bf16
__device__ __nv_bfloat16 g_wvb[DD*DD];       // Wv transposed [n][k] bf16
__device__ float g_q[SROWS*DD];
__device__ float g_attn[BB*NN*16];           // softmax probs, s-padded to 16
__device__ float g_lpart[BB*NCHUNK*16];
__device__ float g_inv[SROWS];
__device__ float g_upart[BB*NCHUNK*SS*DD];
__device__ float g_upd[SROWS*DD];
__device__ float g_gi[SROWS*3*DD];
__device__ float g_gh[SROWS*3*DD];
__device__ float g_stmp[SROWS*DD];
__device__ float g_sA[SROWS*DD];
__device__ float g_sB[SROWS*DD];
__device__ float g_lnb[SROWS*DD];
__device__ float g_h1[SROWS*MLPD];

// ---------------- W transpose + bf16 convert (one-time, tiny) ----------------
__global__ void wtrans_kernel(const float* __restrict__ Wk, const float* __restrict__ Wv,
                              __nv_bfloat16* __restrict__ Ko, __nv_bfloat16* __restrict__ Vo)
{
    __shared__ float tile[32][33];
    const float* src = blockIdx.z ? Wv : Wk;
    __nv_bfloat16* dst = blockIdx.z ? Vo : Ko;
    int k0 = blockIdx.x * 32, n0 = blockIdx.y * 32;
    int tx = threadIdx.x, ty = threadIdx.y;
    tile[ty][tx] = src[(size_t)(k0 + ty) * DD + n0 + tx];
    __syncthreads();
    dst[(size_t)(n0 + ty) * DD + k0 + tx] = __float2bfloat16(tile[tx][ty]);
}

// ---------------- Row LayerNorm -> bf16 out (for inputs) ----------------
__global__ void __launch_bounds__(256) rowln_bf16_kernel(
    const float* __restrict__ X, const float* __restrict__ g,
    const float* __restrict__ b, __nv_bfloat16* __restrict__ out)
{
    int row = blockIdx.x;
    int t = threadIdx.x;
    const float* x = X + (size_t)row * DD;
    float2 v = *(const float2*)(x + 2 * t);
    float s = v.x + v.y;
    float sq = v.x * v.x + v.y * v.y;
    int w = t >> 5, lane = t & 31;
    #pragma unroll
    for (int o = 16; o; o >>= 1) {
        s  += __shfl_xor_sync(0xffffffffu, s, o);
        sq += __shfl_xor_sync(0xffffffffu, sq, o);
    }
    __shared__ float shs[8], shq[8];
    __shared__ float mu_s, rs_s;
    if (lane == 0) { shs[w] = s; shq[w] = sq; }
    __syncthreads();
    if (t == 0) {
        float S = 0.f, Q = 0.f;
        #pragma unroll
        for (int i = 0; i < 8; i++) { S += shs[i]; Q += shq[i]; }
        float mu = S * (1.f / DD);
        float var = Q * (1.f / DD) - mu * mu;
        mu_s = mu;
        rs_s = rsqrtf(var + EPS_LN);
    }
    __syncthreads();
    float mu = mu_s, rs = rs_s;
    float2 gg = *(const float2*)(g + 2 * t);
    float2 bb = *(const float2*)(b + 2 * t);
    float o0 = (v.x - mu) * rs * gg.x + bb.x;
    float o1 = (v.y - mu) * rs * gg.y + bb.y;
    *(__nv_bfloat162*)(out + (size_t)row * DD + 2 * t) = __floats2bfloat162_rn(o0, o1);
}

// ---------------- Row LayerNorm fp32 (for slots; rows of 512) ----------------
__global__ void __launch_bounds__(256) rowln_kernel(
    const float* __restrict__ X, const float* __restrict__ g,
    const float* __restrict__ b, float* __restrict__ out)
{
    int row = blockIdx.x;
    int t = threadIdx.x;
    const float* x = X + (size_t)row * DD;
    float v0 = x[t], v1 = x[t + 256];
    float s = v0 + v1;
    float sq = v0 * v0 + v1 * v1;
    int w = t >> 5, lane = t & 31;
    #pragma unroll
    for (int o = 16; o; o >>= 1) {
        s  += __shfl_xor_sync(0xffffffffu, s, o);
        sq += __shfl_xor_sync(0xffffffffu, sq, o);
    }
    __shared__ float shs[8], shq[8];
    __shared__ float mu_s, rs_s;
    if (lane == 0) { shs[w] = s; shq[w] = sq; }
    __syncthreads();
    if (t == 0) {
        float S = 0.f, Q = 0.f;
        #pragma unroll
        for (int i = 0; i < 8; i++) { S += shs[i]; Q += shq[i]; }
        float mu = S * (1.f / DD);
        float var = Q * (1.f / DD) - mu * mu;
        mu_s = mu;
        rs_s = rsqrtf(var + EPS_LN);
    }
    __syncthreads();
    float mu = mu_s, rs = rs_s;
    float* o = out + (size_t)row * DD;
    o[t]       = (v0 - mu) * rs * g[t]       + b[t];
    o[t + 256] = (v1 - mu) * rs * g[t + 256] + b[t + 256];
}

// ---------------- bf16 TC GEMM w/ cp.async double buffering --------------------
// K|V = xlnb @ W^T(+bias), bf16 out. 128x128 tile, BK=32, 256 threads
// (8 warps: 2m x 4n, warp tile 64x32). mma.m16n8k16 bf16, fp32 accum.
__global__ void __launch_bounds__(256) kv_gemm_bf16_kernel(
    const __nv_bfloat16* __restrict__ A,
    const __nv_bfloat16* __restrict__ Wkb, const __nv_bfloat16* __restrict__ Wvb,
    const float* __restrict__ bk, const float* __restrict__ bv,
    __nv_bfloat16* __restrict__ Kout, __nv_bfloat16* __restrict__ Vout)
{
    __shared__ __align__(16) uint32_t As32[2][128][20];  // [stage][m][k2]
    __shared__ __align__(16) uint32_t Bs32[2][128][20];  // [stage][n][k2]
    int by = blockIdx.x;                 // 0..7 (column block; 0-3 K, 4-7 V)
    int m0 = blockIdx.y * 128;
    const __nv_bfloat16* W; const float* bias; __nv_bfloat16* Dst; int cb;
    if (by < 4) { W = Wkb; bias = bk; Dst = Kout; cb = by * 128; }
    else        { W = Wvb; bias = bv; Dst = Vout; cb = (by - 4) * 128; }

    int t = threadIdx.x;
    int warp = t >> 5, lane = t & 31;
    int wm = (warp & 1) * 64;
    int wn = (warp >> 1) * 32;
    int g = lane >> 2, t4 = lane & 3;

    const uint4* A4 = (const uint4*)A;       // 64 uint4 per 512-col row
    const uint4* W4 = (const uint4*)W;

    float c[4][4][4];
    #pragma unroll
    for (int i = 0; i < 4; i++)
        #pragma unroll
        for (int j = 0; j < 4; j++)
            #pragma unroll
            for (int r = 0; r < 4; r++) c[i][j][r] = 0.f;

#define KV_LOAD(st, kk0) do {                                                   \
        _Pragma("unroll")                                                       \
        for (int i = 0; i < 2; i++) {                                           \
            int item = t + i * 256;                                             \
            int rm = item >> 2, aq = item & 3;                                  \
            const uint4* ga = A4 + (size_t)(m0 + rm) * 64 + ((kk0) >> 3) + aq;  \
            uint32_t sa = (uint32_t)__cvta_generic_to_shared(&As32[st][rm][aq*4]);\
            asm volatile("cp.async.cg.shared.global [%0], [%1], 16;\n"          \
                         :: "r"(sa), "l"(ga));                                  \
            const uint4* gb = W4 + (size_t)(cb + rm) * 64 + ((kk0) >> 3) + aq;  \
            uint32_t sb = (uint32_t)__cvta_generic_to_shared(&Bs32[st][rm][aq*4]);\
            asm volatile("cp.async.cg.shared.global [%0], [%1], 16;\n"          \
                         :: "r"(sb), "l"(gb));                                  \
        }                                                                       \
    } while (0)

    KV_LOAD(0, 0);
    asm volatile("cp.async.commit_group;\n");

    for (int it = 0; it < 16; it++) {
        int st = it & 1;
        if (it < 15) {
            KV_LOAD(st ^ 1, (it + 1) * 32);
            asm volatile("cp.async.commit_group;\n");
            asm volatile("cp.async.wait_group 1;\n");
        } else {
            asm volatile("cp.async.wait_group 0;\n");
        }
        __syncthreads();

        #pragma unroll
        for (int ks = 0; ks < 2; ks++) {
            int kb2 = ks * 8;
            uint32_t a[4][4], bf[4][2];
            #pragma unroll
            for (int i = 0; i < 4; i++) {
                int mb = wm + i * 16;
                a[i][0] = As32[st][mb + g][kb2 + t4];
                a[i][1] = As32[st][mb + g + 8][kb2 + t4];
                a[i][2] = As32[st][mb + g][kb2 + t4 + 4];
                a[i][3] = As32[st][mb + g + 8][kb2 + t4 + 4];
            }
            #pragma unroll
            for (int j = 0; j < 4; j++) {
                int nb = wn + j * 8;
                bf[j][0] = Bs32[st][nb + g][kb2 + t4];
                bf[j][1] = Bs32[st][nb + g][kb2 + t4 + 4];
            }
            #pragma unroll
            for (int i = 0; i < 4; i++)
                #pragma unroll
                for (int j = 0; j < 4; j++) {
                    asm volatile(
                        "mma.sync.aligned.m16n8k16.row.col.f32.bf16.bf16.f32 "
                        "{%0,%1,%2,%3}, {%4,%5,%6,%7}, {%8,%9}, {%0,%1,%2,%3};\n"
                        : "+f"(c[i][j][0]), "+f"(c[i][j][1]),
                          "+f"(c[i][j][2]), "+f"(c[i][j][3])
                        : "r"(a[i][0]), "r"(a[i][1]), "r"(a[i][2]), "r"(a[i][3]),
                          "r"(bf[j][0]), "r"(bf[j][1]));
                }
        }
        __syncthreads();
    }
#undef KV_LOAD

    // epilogue: bias add, convert bf16x2, store. Dst row stride 512 bf16 = 256 u32.
    uint32_t* D32 = (uint32_t*)Dst;
    #pragma unroll
    for (int i = 0; i < 4; i++) {
        int row = m0 + wm + i * 16 + g;
        #pragma unroll
        for (int j = 0; j < 4; j++) {
            int col = wn + j * 8 + t4 * 2;           // within 128-wide tile
            float bx = bias[cb + col], by2 = bias[cb + col + 1];
            int c2 = ((cb + col) >> 1);
            __nv_bfloat162 v0 = __floats2bfloat162_rn(c[i][j][0] + bx, c[i][j][1] + by2);
            __nv_bfloat162 v1 = __floats2bfloat162_rn(c[i][j][2] + bx, c[i][j][3] + by2);
            D32[(size_t)row * 256 + c2] = *(uint32_t*)&v0;
            D32[(size_t)(row + 8) * 256 + c2] = *(uint32_t*)&v1;
        }
    }
}

// ---------------- Small GEMM: C = scale*(A@op(B)) + bias, opt relu ----------------
// 16x64x32 tiles, 128 threads, 2x4 per thread. blockIdx.z selects two problem sets.
__global__ void __launch_bounds__(128) gemm_small_kernel(
    const float* __restrict__ A0, const float* __restrict__ A1,
    const float* __restrict__ B0, const float* __restrict__ B1,
    const float* __restrict__ bias0, const float* __restrict__ bias1,
    float* __restrict__ C0, float* __restrict__ C1,
    int N, int K, int transB, float scale, int relu)
{
    const float* A = blockIdx.z ? A1 : A0;
    const float* Bm = blockIdx.z ? B1 : B0;
    const float* bias = blockIdx.z ? bias1 : bias0;
    float* C = blockIdx.z ? C1 : C0;

    __shared__ __align__(16) float As[32][18];
    __shared__ __align__(16) float Bs[32][68];
    int m0 = blockIdx.x * 16, n0 = blockIdx.y * 64;
    int t = threadIdx.x;
    int tx = t & 15, ty = t >> 4;
    float acc[2][4];
    #pragma unroll
    for (int i = 0; i < 2; i++)
        #pragma unroll
        for (int j = 0; j < 4; j++) acc[i][j] = 0.f;

    for (int k0 = 0; k0 < K; k0 += 32) {
        #pragma unroll
        for (int i = 0; i < 4; i++) {
            int idx = t + i * 128;
            int m = idx >> 5, k = idx & 31;
            As[k][m] = A[(size_t)(m0 + m) * K + k0 + k];
        }
        if (!transB) {
            #pragma unroll
            for (int i = 0; i < 16; i++) {
                int idx = t + i * 128;
                int k = idx >> 6, n = idx & 63;
                Bs[k][n] = Bm[(size_t)(k0 + k) * N + n0 + n];
            }
        } else {
            #pragma unroll
            for (int i = 0; i < 16; i++) {
                int idx = t + i * 128;
                int n = idx >> 5, k = idx & 31;
                Bs[k][n] = Bm[(size_t)(n0 + n) * K + k0 + k];
            }
        }
        __syncthreads();
        #pragma unroll
        for (int kk = 0; kk < 32; kk++) {
            float a0 = As[kk][ty * 2], a1 = As[kk][ty * 2 + 1];
            float4 b = *(const float4*)&Bs[kk][tx * 4];
            acc[0][0] = fmaf(a0, b.x, acc[0][0]);
            acc[0][1] = fmaf(a0, b.y, acc[0][1]);
            acc[0][2] = fmaf(a0, b.z, acc[0][2]);
            acc[0][3] = fmaf(a0, b.w, acc[0][3]);
            acc[1][0] = fmaf(a1, b.x, acc[1][0]);
            acc[1][1] = fmaf(a1, b.y, acc[1][1]);
            acc[1][2] = fmaf(a1, b.z, acc[1][2]);
            acc[1][3] = fmaf(a1, b.w, acc[1][3]);
        }
        __syncthreads();
    }
    float4 bvv = make_float4(0.f, 0.f, 0.f, 0.f);
    if (bias) bvv = *(const float4*)(bias + n0 + tx * 4);
    #pragma unroll
    for (int i = 0; i < 2; i++) {
        int m = m0 + ty * 2 + i;
        float4 v;
        v.x = acc[i][0] * scale + bvv.x;
        v.y = acc[i][1] * scale + bvv.y;
        v.z = acc[i][2] * scale + bvv.z;
        v.w = acc[i][3] * scale + bvv.w;
        if (relu) {
            v.x = fmaxf(v.x, 0.f); v.y = fmaxf(v.y, 0.f);
            v.z = fmaxf(v.z, 0.f); v.w = fmaxf(v.w, 0.f);
        }
        *(float4*)(C + (size_t)m * N + n0 + tx * 4) = v;
    }
}

// ------- Tensor-core logits + softmax(over S) + renorm partials -----------------
// Block = (b, n-chunk of 256). Warp w owns n cols [w*32, w*32+32).
// mma.m16n8k16: A = q(bf16, s padded to 16), B = K (bf16 [n][k] = col-major).
__global__ void __launch_bounds__(256) logits_softmax_tc_kernel(
    const float* __restrict__ q, const __nv_bfloat16* __restrict__ Kb,
    float* __restrict__ attn, float* __restrict__ lpart)
{
    __shared__ __align__(16) uint32_t Qs32[16][20];    // [s][k2]
    __shared__ __align__(16) uint32_t Ks32[256][20];   // [n][k2]
    __shared__ float St[16 * 260];                     // logits stash / probs
    int b = blockIdx.x, chunk = blockIdx.y;
    int t = threadIdx.x;
    int warp = t >> 5, lane = t & 31;
    int g = lane >> 2, t4 = lane & 3;
    int n0 = chunk * 256;
    const uint4* kb4 = (const uint4*)(Kb + ((size_t)b * NN + n0) * DD);  // 64 u4/row

    float c[4][4];
    #pragma unroll
    for (int j = 0; j < 4; j++)
        #pragma unroll
        for (int r = 0; r < 4; r++) c[j][r] = 0.f;

    for (int k0 = 0; k0 < DD; k0 += 32) {
        {   // Q: 16 s x 32 k bf16 (convert from fp32) = 256 u32, 1 per thread
            int s = t >> 4, k2 = t & 15;
            float2 f = make_float2(0.f, 0.f);
            if (s < SS) f = *(const float2*)(q + (size_t)(b * SS + s) * DD + k0 + k2 * 2);
            __nv_bfloat162 h = __floats2bfloat162_rn(f.x, f.y);
            Qs32[s][k2] = *(uint32_t*)&h;
        }
        // K tile: 256 n x 32 k bf16 = 1024 u4, 4 per thread
        #pragma unroll
        for (int i = 0; i < 4; i++) {
            int item = t + i * 256;
            int n = item >> 2, aq = item & 3;
            uint4 v = kb4[(size_t)n * 64 + (k0 >> 3) + aq];
            *(uint4*)&Ks32[n][aq * 4] = v;
        }
        __syncthreads();
        #pragma unroll
        for (int ks = 0; ks < 2; ks++) {
            int kb2 = ks * 8;
            uint32_t a[4];
            a[0] = Qs32[g][kb2 + t4];
            a[1] = Qs32[g + 8][kb2 + t4];
            a[2] = Qs32[g][kb2 + t4 + 4];
            a[3] = Qs32[g + 8][kb2 + t4 + 4];
            #pragma unroll
            for (int j = 0; j < 4; j++) {
                int nb = warp * 32 + j * 8;
                uint32_t b0 = Ks32[nb + g][kb2 + t4];
                uint32_t b1 = Ks32[nb + g][kb2 + t4 + 4];
                asm volatile(
                    "mma.sync.aligned.m16n8k16.row.col.f32.bf16.bf16.f32 "
                    "{%0,%1,%2,%3}, {%4,%5,%6,%7}, {%8,%9}, {%0,%1,%2,%3};\n"
                    : "+f"(c[j][0]), "+f"(c[j][1]), "+f"(c[j][2]), "+f"(c[j][3])
                    : "r"(a[0]), "r"(a[1]), "r"(a[2]), "r"(a[3]),
                      "r"(b0), "r"(b1));
            }
        }
        __syncthreads();
    }

    // stash logits [s][n]
    #pragma unroll
    for (int j = 0; j < 4; j++) {
        int nb = warp * 32 + j * 8;
        St[g * 260 + nb + t4 * 2]           = c[j][0];
        St[g * 260 + nb + t4 * 2 + 1]       = c[j][1];
        St[(g + 8) * 260 + nb + t4 * 2]     = c[j][2];
        St[(g + 8) * 260 + nb + t4 * 2 + 1] = c[j][3];
    }
    __syncthreads();

    // per-n softmax over s (each thread owns one n)
    float p[SS];
    {
        int n = t;
        float m = -1e30f;
        #pragma unroll
        for (int s = 0; s < SS; s++) m = fmaxf(m, St[s * 260 + n]);
        float sum = 0.f;
        #pragma unroll
        for (int s = 0; s < SS; s++) { float e = __expf(St[s * 260 + n] - m); p[s] = e; sum += e; }
        float r = 1.f / sum;
        float* ar = attn + ((size_t)b * NN + n0 + n) * 16;
        #pragma unroll
        for (int s = 0; s < SS; s++) { p[s] *= r; ar[s] = p[s]; }
    }
    __syncthreads();
    #pragma unroll
    for (int s = 0; s < SS; s++) St[s * 260 + t] = p[s];
    __syncthreads();

    int w = t >> 5, lane2 = t & 31;
    for (int s = w; s < SS; s += 8) {
        float v = 0.f;
        #pragma unroll
        for (int i = 0; i < 8; i++) v += St[s * 260 + lane2 + i * 32];
        #pragma unroll
        for (int o = 16; o; o >>= 1) v += __shfl_xor_sync(0xffffffffu, v, o);
        if (lane2 == 0) lpart[(b * NCHUNK + chunk) * 16 + s] = v;
    }
}

// ---------------- inv = 1/(sum_n attn + eps) ----------------
__global__ void inv_kernel(const float* __restrict__ lpart, float* __restrict__ inv)
{
    int t = threadIdx.x;
    if (t < SROWS) {
        int b = t / SS, s = t % SS;
        float sum = 0.f;
        #pragma unroll
        for (int c = 0; c < NCHUNK; c++) sum += lpart[(b * NCHUNK + c) * 16 + s];
        inv[t] = 1.f / (sum + EPS_ATTN);
    }
}

// ---------------- updates partials (V bf16) ----------------
__device__ __forceinline__ void fma4(float4& a, float s, float4 v) {
    a.x = fmaf(s, v.x, a.x); a.y = fmaf(s, v.y, a.y);
    a.z = fmaf(s, v.z, a.z); a.w = fmaf(s, v.w, a.w);
}

__global__ void __launch_bounds__(128) updates_kernel(
    const __nv_bfloat16* __restrict__ Vb, const float* __restrict__ attn,
    float* __restrict__ upart)
{
    int b = blockIdx.x, chunk = blockIdx.y, t = threadIdx.x;
    float4 acc[SS];
    #pragma unroll
    for (int s = 0; s < SS; s++) acc[s] = make_float4(0.f, 0.f, 0.f, 0.f);
    const __nv_bfloat16* vb = Vb + (size_t)b * NN * DD;
    const float* pb = attn + (size_t)b * NN * 16;
    int n0 = chunk * 256;
    for (int n = n0; n < n0 + 256; n++) {
        uint2 raw = *(const uint2*)(vb + (size_t)n * DD + t * 4);
        __nv_bfloat162 h0 = *(__nv_bfloat162*)&raw.x;
        __nv_bfloat162 h1 = *(__nv_bfloat162*)&raw.y;
        float2 f0 = __bfloat1622float2(h0);
        float2 f1 = __bfloat1622float2(h1);
        float4 v = make_float4(f0.x, f0.y, f1.x, f1.y);
        const float* pr = pb + (size_t)n * 16;
        float4 p0 = *(const float4*)(pr);
        float4 p1 = *(const float4*)(pr + 4);
        float4 p2 = *(const float4*)(pr + 8);
        fma4(acc[0],  p0.x, v); fma4(acc[1],  p0.y, v);
        fma4(acc[2],  p0.z, v); fma4(acc[3],  p0.w, v);
        fma4(acc[4],  p1.x, v); fma4(acc[5],  p1.y, v);
        fma4(acc[6],  p1.z, v); fma4(acc[7],  p1.w, v);
        fma4(acc[8],  p2.x, v); fma4(acc[9],  p2.y, v);
        fma4(acc[10], p2.z, v);
    }
    #pragma unroll
    for (int s = 0; s < SS; s++)
        *(float4*)(upart + ((size_t)((b * NCHUNK + chunk) * SS + s)) * DD + t * 4) = acc[s];
}

// ---------------- reduce partials + apply renorm ----------------
__global__ void __launch_bounds__(128) upd_reduce_kernel(
    const float* __restrict__ upart, const float* __restrict__ inv,
    float* __restrict__ upd)
{
    int row = blockIdx.x;
    int b = row / SS, s = row % SS;
    int t = threadIdx.x;
    float4 acc = make_float4(0.f, 0.f, 0.f, 0.f);
    for (int c = 0; c < NCHUNK; c++) {
        float4 v = *(const float4*)(upart + ((size_t)((b * NCHUNK + c) * SS + s)) * DD + t * 4);
        acc.x += v.x; acc.y += v.y; acc.z += v.z; acc.w += v.w;
    }
    float iv = inv[row];
    acc.x *= iv; acc.y *= iv; acc.z *= iv; acc.w *= iv;
    *(float4*)(upd + (size_t)row * DD + t * 4) = acc;
}

// ---------------- GRU elementwise ----------------
__global__ void __launch_bounds__(256) gru_kernel(
    const float* __restrict__ gi, const float* __restrict__ gh,
    const float* __restrict__ slots, float* __restrict__ out)
{
    int idx = blockIdx.x * 256 + threadIdx.x;
    if (idx >= SROWS * DD) return;
    int row = idx >> 9, d = idx & 511;
    size_t base = (size_t)row * (3 * DD);
    float ir = gi[base + d], iz = gi[base + DD + d], inn = gi[base + 2 * DD + d];
    float hr = gh[base + d], hz = gh[base + DD + d], hn = gh[base + 2 * DD + d];
    float r = 1.f / (1.f + __expf(-(ir + hr)));
    float z = 1.f / (1.f + __expf(-(iz + hz)));
    float nn = tanhf(inn + r * hn);
    out[idx] = (1.f - z) * nn + z * slots[idx];
}

// ---------------- Host orchestration ----------------
extern "C" void kernel_launch(void* const* d_in, const int* in_sizes, int n_in,
                              void* d_out, int out_size)
{
    const float* slots0  = (const float*)d_in[0];
    const float* inputs  = (const float*)d_in[1];
    const float* ln_in_g = (const float*)d_in[2];
    const float* ln_in_b = (const float*)d_in[3];
    const float* Wk      = (const float*)d_in[4];
    const float* bk      = (const float*)d_in[5];
    const float* Wv      = (const float*)d_in[6];
    const float* bv      = (const float*)d_in[7];
    const float* ln_q_g  = (const float*)d_in[8];
    const float* ln_q_b  = (const float*)d_in[9];
    const float* Wq      = (const float*)d_in[10];
    const float* W_ih    = (const float*)d_in[11];
    const float* b_ih    = (const float*)d_in[12];
    const float* W_hh    = (const float*)d_in[13];
    const float* b_hh    = (const float*)d_in[14];
    const float* ln_m_g  = (const float*)d_in[15];
    const float* ln_m_b  = (const float*)d_in[16];
    const float* W1      = (const float*)d_in[17];
    const float* b1      = (const float*)d_in[18];
    const float* W2      = (const float*)d_in[19];
    const float* b2      = (const float*)d_in[20];
    float* out = (float*)d_out;

    __nv_bfloat16 *xlnb, *kb, *vb2, *wkb, *wvb;
    float *qp, *attn, *lpart, *invp, *upart, *upd, *gi, *gh;
    float *stmp, *sA, *sB, *lnb, *h1;
    cudaGetSymbolAddress((void**)&xlnb, g_xlnb);
    cudaGetSymbolAddress((void**)&kb,   g_kb);
    cudaGetSymbolAddress((void**)&vb2,  g_vb);
    cudaGetSymbolAddress((void**)&wkb,  g_wkb);
    cudaGetSymbolAddress((void**)&wvb,  g_wvb);
    cudaGetSymbolAddress((void**)&qp,   g_q);
    cudaGetSymbolAddress((void**)&attn, g_attn);
    cudaGetSymbolAddress((void**)&lpart,g_lpart);
    cudaGetSymbolAddress((void**)&invp, g_inv);
    cudaGetSymbolAddress((void**)&upart,g_upart);
    cudaGetSymbolAddress((void**)&upd,  g_upd);
    cudaGetSymbolAddress((void**)&gi,   g_gi);
    cudaGetSymbolAddress((void**)&gh,   g_gh);
    cudaGetSymbolAddress((void**)&stmp, g_stmp);
    cudaGetSymbolAddress((void**)&sA,   g_sA);
    cudaGetSymbolAddress((void**)&sB,   g_sB);
    cudaGetSymbolAddress((void**)&lnb,  g_lnb);
    cudaGetSymbolAddress((void**)&h1,   g_h1);

    const float qscale = 0.044194173824159216f; // 1/sqrt(512)

    // one-time: W transpose->bf16, input LN->bf16, kv GEMM (bf16 TC + cp.async)
    wtrans_kernel<<<dim3(16, 16, 2), dim3(32, 32)>>>(Wk, Wv, wkb, wvb);
    rowln_bf16_kernel<<<MROWS, 256>>>(inputs, ln_in_g, ln_in_b, xlnb);
    kv_gemm_bf16_kernel<<<dim3(8, MROWS / 128), 256>>>(xlnb, wkb, wvb, bk, bv, kb, vb2);

    const float* cur = slots0;
    for (int it = 0; it < 3; it++) {
        // q = LN(slots) @ Wq * scale
        rowln_kernel<<<SROWS, 256>>>(cur, ln_q_g, ln_q_b, lnb);
        gemm_small_kernel<<<dim3(22, 8, 1), 128>>>(
            lnb, lnb, Wq, Wq, nullptr, nullptr, qp, qp,
            DD, DD, 0, qscale, 0);
        // inverted attention (tensor-core logits)
        logits_softmax_tc_kernel<<<dim3(BB, NCHUNK), 256>>>(qp, kb, attn, lpart);
        inv_kernel<<<1, 384>>>(lpart, invp);
        updates_kernel<<<dim3(BB, NCHUNK), 128>>>(vb2, attn, upart);
        upd_reduce_kernel<<<SROWS, 128>>>(upart, invp, upd);
        // GRU gates (one launch for both)
        gemm_small_kernel<<<dim3(22, 24, 2), 128>>>(
            upd, cur, W_ih, W_hh, b_ih, b_hh, gi, gh,
            3 * DD, DD, 1, 1.f, 0);
        gru_kernel<<<(SROWS * DD + 255) / 256, 256>>>(gi, gh, cur, stmp);
        // MLP (no residual)
        rowln_kernel<<<SROWS, 256>>>(stmp, ln_m_g, ln_m_b, lnb);
        gemm_small_kernel<<<dim3(22, 32, 1), 128>>>(
            lnb, lnb, W1, W1, b1, b1, h1, h1,
            MLPD, DD, 0, 1.f, 1);
        float* nxt = (it == 2) ? out : (it == 0 ? sA : sB);
        gemm_small_kernel<<<dim3(22, 8, 1), 128>>>(
            h1, h1, W2, W2, b2, b2, nxt, nxt,
            DD, MLPD, 0, 1.f, 0);
        cur = nxt;
    }
}